// round 10
// baseline (speedup 1.0000x reference)
#include <cuda_runtime.h>

typedef unsigned long long ull;

#define NBLK 128
#define BH   65536
#define Tq   40
#define VOCq 10000

__device__ float g_P[3][Tq * BH];
__device__ float g_C[3][BH];
__device__ float g_H0B[2][BH];
__device__ float g_H1[BH];
__device__ float g_Z0[BH];
__device__ float g_RH0[BH];
__device__ float g_Z1[BH];
__device__ float g_RH1[BH];
__device__ float g_H1seq[Tq * BH];
__device__ unsigned g_cnt;

__device__ __forceinline__ ull pk2(float x, float y) {
    ull r; asm("mov.b64 %0, {%1,%2};" : "=l"(r) : "f"(x), "f"(y)); return r;
}
__device__ __forceinline__ void upk2(ull v, float &x, float &y) {
    asm("mov.b64 {%0,%1}, %2;" : "=f"(x), "=f"(y) : "l"(v));
}
__device__ __forceinline__ void fma2(ull &c, ull a, ull b) {
    asm("fma.rn.f32x2 %0, %1, %2, %3;" : "=l"(c) : "l"(a), "l"(b), "l"(c));
}

__device__ __forceinline__ void gridbar(unsigned &target) {
    __syncthreads();
    target += NBLK;
    if (threadIdx.x == 0) {
        asm volatile("red.release.gpu.add.u32 [%0], %1;" :: "l"(&g_cnt), "r"(1u) : "memory");
        unsigned v, ns = 64;
        while (true) {
            asm volatile("ld.acquire.gpu.u32 %0, [%1];" : "=r"(v) : "l"(&g_cnt) : "memory");
            if ((int)(v - target) >= 0) break;
            __nanosleep(ns);
            if (ns < 256) ns <<= 1;
        }
    }
    __syncthreads();
}

// ---------------- warp-N-split recurrence tile ----------------
// BMx64 tile, 256 threads, 8 warps. Warp w owns cols [8w,8w+8) ONLY
// (8x less W crossbar traffic). Lane (r=lane>>2, c=lane&3) computes
// rows TM*r..TM*r+TM-1 x cols {8w+2c, 8w+2c+1}. A is duplicated in smem
// with a permuted pair layout so the lane's TM dup-rows are contiguous
// conflict-free LDS128s. mode 0: sigm(v+add)[*mulS]; mode 1: GRU update.
template<int BM>
__device__ __noinline__ void gtile(float *sA, float *sW, int m0, int n0, int K,
    const float *A1, const float *A2, const float *W,
    const float *addRow, const float *addMat, int mode,
    const float *mulS, const float *hPrev, const float *zG,
    float *dst, float *dst2)
{
    constexpr int TM    = BM / 8;          // 4 (BM=32) or 2 (BM=16)
    constexpr int PITCH = 2 * BM + 4;      // 68 / 36 floats (16B-aligned)
    constexpr int TPR   = 32 / TM;         // staging threads per m-row
    const int tid = threadIdx.x, lane = tid & 31, w = tid >> 5;
    const int r = lane >> 2, c = lane & 3;

    // staging: one m-row, TM consecutive k's per thread
    const int sm = tid / TPR;
    const int sk = (tid % TPR) * TM;
    int pm;                                 // permuted dup-pair position of row sm
    if (BM == 32) { int g = sm >> 2, q = sm & 3;
                    pm = (q < 2) ? (2 * g + q) : (16 + 2 * g + (q - 2)); }
    else pm = sm;
    const int soff = 2 * pm;

    __syncthreads();                        // smem reuse across calls

    ull acc[TM];
#pragma unroll
    for (int i = 0; i < TM; i++) acc[i] = 0ull;

    auto ald = [&](int kb, int j) -> float {
        int k = kb + sk + j;
        const float *b = (k < 512) ? A1 : A2;
        return b[(m0 + sm) * 512 + (k & 511)];
    };

    float ra[TM]; float4 rw[2];
#pragma unroll
    for (int j = 0; j < TM; j++) ra[j] = ald(0, j);
#pragma unroll
    for (int j = 0; j < 2; j++) {
        int q = tid + j * 256;
        rw[j] = *(const float4 *)(W + (size_t)(q >> 4) * 512 + n0 + (q & 15) * 4);
    }
#pragma unroll
    for (int j = 0; j < TM; j++)
        *(ull *)(sA + (sk + j) * PITCH + soff) = pk2(ra[j], ra[j]);
#pragma unroll
    for (int j = 0; j < 2; j++) {
        int q = tid + j * 256;
        *(float4 *)(sW + (q >> 4) * 64 + (q & 15) * 4) = rw[j];
    }
    __syncthreads();

    const int niter = K >> 5;
    for (int it = 0; it < niter; ++it) {
        if (it + 1 < niter) {
            int kb = (it + 1) << 5;
#pragma unroll
            for (int j = 0; j < TM; j++) ra[j] = ald(kb, j);
#pragma unroll
            for (int j = 0; j < 2; j++) {
                int q = tid + j * 256;
                rw[j] = *(const float4 *)(W + (size_t)(kb + (q >> 4)) * 512 + n0 + (q & 15) * 4);
            }
        }
        const float *A0 = sA + (it & 1) * 32 * PITCH;
        const float *W0 = sW + (it & 1) * 32 * 64;
#pragma unroll
        for (int kk = 0; kk < 32; kk++) {
            ull au[TM];
            {
                ulonglong2 v1 = *(const ulonglong2 *)(A0 + kk * PITCH + 4 * r);
                au[0] = v1.x; au[1] = v1.y;
                if (BM == 32) {
                    ulonglong2 v2 = *(const ulonglong2 *)(A0 + kk * PITCH + 32 + 4 * r);
                    au[2] = v2.x; au[3] = v2.y;
                }
            }
            ull wv = *(const ull *)(W0 + kk * 64 + 8 * w + 2 * c);
#pragma unroll
            for (int i = 0; i < TM; i++) fma2(acc[i], au[i], wv);
        }
        if (it + 1 < niter) {
            float *An = sA + ((it + 1) & 1) * 32 * PITCH;
            float *Wn = sW + ((it + 1) & 1) * 32 * 64;
#pragma unroll
            for (int j = 0; j < TM; j++)
                *(ull *)(An + (sk + j) * PITCH + soff) = pk2(ra[j], ra[j]);
#pragma unroll
            for (int j = 0; j < 2; j++) {
                int q = tid + j * 256;
                *(float4 *)(Wn + (q >> 4) * 64 + (q & 15) * 4) = rw[j];
            }
            __syncthreads();
        }
    }

#pragma unroll
    for (int i = 0; i < TM; i++) {
        float lh[2]; upk2(acc[i], lh[0], lh[1]);
        int row = m0 + TM * r + i, c0 = n0 + 8 * w + 2 * c;
#pragma unroll
        for (int e = 0; e < 2; e++) {
            int col = c0 + e, idx = row * 512 + col;
            float x = lh[e] + (addRow ? addRow[col] : addMat[idx]);
            if (mode == 0) {
                float s = __fdividef(1.f, 1.f + __expf(-x));
                dst[idx] = mulS ? s * mulS[idx] : s;
            } else {
                float ex = __expf(2.f * x);
                float hh = 1.f - __fdividef(2.f, ex + 1.f);
                float z = zG[idx];
                float hn = z * hPrev[idx] + (1.f - z) * hh;
                dst[idx] = hn;
                if (dst2) dst2[idx] = hn;
            }
        }
    }
}

// ---------------- persistent recurrence (mapping unchanged) ----------------
__global__ __launch_bounds__(256, 2) void k_recur(
    const float *wu0, const float *wr0, const float *wc0,
    const float *wu1, const float *bu1, const float *wr1, const float *br1,
    const float *wc1, const float *bc1)
{
    __shared__ __align__(16) float sA[2 * 32 * 68];
    __shared__ __align__(16) float sW[2 * 32 * 64];
    unsigned target = 0;
    const int b = blockIdx.x;

    auto ZR = [&](int t) {
        if (b < 64) {                                   // ZR1(t), K=1024
            if (t < 0) return;
            int gate = b >> 5, id = b & 31;
            int m0 = (id >> 3) * 32, n0 = (id & 7) * 64;
            gtile<32>(sA, sW, m0, n0, 1024, g_H1, g_H0B[t & 1],
                      gate ? wr1 : wu1, gate ? br1 : bu1, nullptr, 0,
                      gate ? (const float *)g_H1 : nullptr, nullptr, nullptr,
                      gate ? g_RH1 : g_Z1, nullptr);
        } else {                                        // ZR0(t+1), K=512
            int tn = t + 1;
            if (tn > 39) return;
            int s = b - 64, gate = s >> 5, id = s & 31;
            int m0 = (id >> 3) * 32, n0 = (id & 7) * 64;
            const float *Hp = g_H0B[t & 1];             // t=-1 -> buf1 (zeros)
            gtile<32>(sA, sW, m0, n0, 512, Hp, Hp,
                      gate ? wr0 : wu0, nullptr, g_P[gate] + (size_t)tn * BH, 0,
                      gate ? Hp : nullptr, nullptr, nullptr,
                      gate ? g_RH0 : g_Z0, nullptr);
        }
    };
    auto HP = [&](int t) {
        if (b < 64) {                                   // H1(t-1), K=1024
            int tp = t - 1;
            if (tp < 0) return;
            int m0 = (b >> 3) * 16, n0 = (b & 7) * 64;
            gtile<16>(sA, sW, m0, n0, 1024, g_RH1, g_H0B[tp & 1], wc1,
                      bc1, nullptr, 1, nullptr, g_H1, g_Z1,
                      g_H1, g_H1seq + (size_t)tp * BH);
        } else {                                        // H0(t), K=512
            if (t > 39) return;
            int s = b - 64, m0 = (s >> 3) * 16, n0 = (s & 7) * 64;
            gtile<16>(sA, sW, m0, n0, 512, g_RH0, g_RH0, wc0,
                      nullptr, g_P[2] + (size_t)t * BH, 1,
                      nullptr, g_H0B[(t - 1) & 1], g_Z0,
                      g_H0B[t & 1], nullptr);
        }
    };

    ZR(-1); gridbar(target);
    for (int t = 0; t < Tq; t++) {
        HP(t); gridbar(target);
        ZR(t); gridbar(target);
    }
    HP(Tq);
}

// ---------------- big parallel GEMM core (unchanged) ----------------
template<int BM, int BN, int BK, int TM, int TN, int THREADS,
         class AF, class WF, class EF>
__device__ __forceinline__ void core(float *sA, float *sW, int tid,
                                     int K, AF aload, WF wload, EF epi)
{
    constexpr int NT = BN / TN, MT = BM / TM, TN2 = TN / 2;
    constexpr int AS = 2 * BM + 4;
    constexpr int ALD = BM * BK / THREADS, WLD = BK * BN / THREADS;
    static_assert(NT * MT == THREADS, "");
    const int tx = tid % NT, ty = tid / NT;
    __syncthreads();
    ull acc[TM][TN2];
#pragma unroll
    for (int i = 0; i < TM; i++)
#pragma unroll
        for (int j = 0; j < TN2; j++) acc[i][j] = 0ull;
#pragma unroll
    for (int j = 0; j < ALD; j++) {
        int idx = tid + j * THREADS;
        float v = aload(idx % BK, idx / BK);
        *(ull *)(sA + (idx % BK) * AS + 2 * (idx / BK)) = pk2(v, v);
    }
#pragma unroll
    for (int j = 0; j < WLD; j++) {
        int idx = tid + j * THREADS;
        sW[(idx / BN) * BN + idx % BN] = wload(idx / BN, idx % BN);
    }
    __syncthreads();
    const int niter = K / BK;
    for (int it = 0; it < niter; ++it) {
        float ra[ALD], rw[WLD];
        if (it + 1 < niter) {
            const int kb = (it + 1) * BK;
#pragma unroll
            for (int j = 0; j < ALD; j++) {
                int idx = tid + j * THREADS;
                ra[j] = aload(kb + idx % BK, idx / BK);
            }
#pragma unroll
            for (int j = 0; j < WLD; j++) {
                int idx = tid + j * THREADS;
                rw[j] = wload(kb + idx / BN, idx % BN);
            }
        }
        const float *A0 = sA + (it & 1) * BK * AS;
        const float *W0 = sW + (it & 1) * BK * BN;
#pragma unroll
        for (int kk = 0; kk < BK; kk++) {
            ull au[TM];
            const ulonglong2 *ap = (const ulonglong2 *)(A0 + kk * AS + 2 * ty * TM);
#pragma unroll
            for (int i = 0; i < TM / 2; i++) {
                ulonglong2 v = ap[i]; au[2 * i] = v.x; au[2 * i + 1] = v.y;
            }
            ull wv[TN2];
            const ull *wp = (const ull *)(W0 + kk * BN + tx * TN);
#pragma unroll
            for (int j = 0; j < TN2; j++) wv[j] = wp[j];
#pragma unroll
            for (int i = 0; i < TM; i++)
#pragma unroll
                for (int j = 0; j < TN2; j++) fma2(acc[i][j], au[i], wv[j]);
        }
        if (it + 1 < niter) {
            float *An = sA + ((it + 1) & 1) * BK * AS;
            float *Wn = sW + ((it + 1) & 1) * BK * BN;
#pragma unroll
            for (int j = 0; j < ALD; j++) {
                int idx = tid + j * THREADS;
                *(ull *)(An + (idx % BK) * AS + 2 * (idx / BK)) = pk2(ra[j], ra[j]);
            }
#pragma unroll
            for (int j = 0; j < WLD; j++) {
                int idx = tid + j * THREADS;
                Wn[(idx / BN) * BN + idx % BN] = rw[j];
            }
            __syncthreads();
        }
    }
#pragma unroll
    for (int i = 0; i < TM; i++)
#pragma unroll
        for (int j = 0; j < TN2; j++) {
            float lo, hi; upk2(acc[i][j], lo, hi);
            epi(ty * TM + i, tx * TN + 2 * j, lo);
            epi(ty * TM + i, tx * TN + 2 * j + 1, hi);
        }
}

__global__ void k_init() {
    int i = blockIdx.x * blockDim.x + threadIdx.x;
    if (i < BH) { g_H0B[1][i] = 0.f; g_H1[i] = 0.f; }
    if (i == 0) g_cnt = 0u;
}

#define BIG_SA (2 * 16 * 132)
#define BIG_SW (2 * 16 * 128)

__global__ __launch_bounds__(256) void k_cnn(const float *cnn,
    const float *wu, const float *wr, const float *wc,
    const float *bu, const float *br, const float *bc)
{
    __shared__ __align__(16) float sA[BIG_SA];
    __shared__ __align__(16) float sW[BIG_SW];
    int g = blockIdx.z, m0 = (blockIdx.x & 1) * 64, n0 = (blockIdx.x >> 1) * 128;
    const float *W    = (g == 0 ? wu : g == 1 ? wr : wc) + 1024 * 512;
    const float *bias = (g == 0 ? bu : g == 1 ? br : bc);
    float *Cout = g_C[g];
    core<64, 128, 16, 8, 4, 256>(sA, sW, threadIdx.x, 512,
        [&](int k, int m) { return cnn[(m0 + m) * 512 + k]; },
        [&](int k, int n) { return W[k * 512 + n0 + n]; },
        [&](int mi, int nj, float v) {
            Cout[(m0 + mi) * 512 + n0 + nj] = v + bias[n0 + nj]; });
}

__global__ __launch_bounds__(256) void k_embed(const int *tokens, const float *emb,
    const float *wu, const float *wr, const float *wc)
{
    __shared__ __align__(16) float sA[BIG_SA];
    __shared__ __align__(16) float sW[BIG_SW];
    __shared__ int rowtok[128];
    int g = blockIdx.z, t = blockIdx.y;
    int m0 = (blockIdx.x & 1) * 64, n0 = (blockIdx.x >> 1) * 128;
    if (threadIdx.x < 128) rowtok[threadIdx.x] = tokens[threadIdx.x * Tq + t];
    __syncthreads();
    const float *W  = (g == 0 ? wu : g == 1 ? wr : wc) + 512 * 512;
    const float *Cg = g_C[g];
    float *Pg = g_P[g] + (size_t)t * BH;
    core<64, 128, 16, 8, 4, 256>(sA, sW, threadIdx.x, 512,
        [&](int k, int m) { return emb[(size_t)rowtok[m0 + m] * 512 + k]; },
        [&](int k, int n) { return W[k * 512 + n0 + n]; },
        [&](int mi, int nj, float v) {
            int idx = (m0 + mi) * 512 + n0 + nj;
            Pg[idx] = v + Cg[idx];
        });
}

__global__ __launch_bounds__(256) void k_logits(const float *ow, const float *ob, float *out)
{
    __shared__ __align__(16) float sA[BIG_SA];
    __shared__ __align__(16) float sW[BIG_SW];
    int t = blockIdx.y;
    int m0 = (blockIdx.x & 1) * 64, n0 = (blockIdx.x >> 1) * 128;
    const float *A = g_H1seq + (size_t)t * BH;
    core<64, 128, 16, 8, 4, 256>(sA, sW, threadIdx.x, 512,
        [&](int k, int m) { return A[(m0 + m) * 512 + k]; },
        [&](int k, int n) { int c = n0 + n; return (c < VOCq) ? ow[(size_t)k * VOCq + c] : 0.f; },
        [&](int mi, int nj, float v) {
            int c = n0 + nj;
            if (c < VOCq) out[((size_t)(m0 + mi) * Tq + t) * VOCq + c] = v + ob[c];
        });
}

__global__ void k_hidden(float *out)
{
    int i = blockIdx.x * blockDim.x + threadIdx.x;
    if (i < BH) { out[i] = g_H0B[1][i]; out[BH + i] = g_H1[i]; }
}

extern "C" void kernel_launch(void *const *d_in, const int *in_sizes, int n_in,
                              void *d_out, int out_size)
{
    const int   *tokens = (const int *)  d_in[0];
    const float *cnn    = (const float *)d_in[1];
    const float *emb    = (const float *)d_in[2];
    const float *wu0 = (const float *)d_in[3],  *bu0 = (const float *)d_in[4];
    const float *wr0 = (const float *)d_in[5],  *br0 = (const float *)d_in[6];
    const float *wc0 = (const float *)d_in[7],  *bc0 = (const float *)d_in[8];
    const float *wu1 = (const float *)d_in[9],  *bu1 = (const float *)d_in[10];
    const float *wr1 = (const float *)d_in[11], *br1 = (const float *)d_in[12];
    const float *wc1 = (const float *)d_in[13], *bc1 = (const float *)d_in[14];
    const float *ow  = (const float *)d_in[15], *ob  = (const float *)d_in[16];
    float *out = (float *)d_out;

    k_init<<<128, 512>>>();
    k_cnn  <<<dim3(8, 1, 3),  256>>>(cnn, wu0, wr0, wc0, bu0, br0, bc0);
    k_embed<<<dim3(8, Tq, 3), 256>>>(tokens, emb, wu0, wr0, wc0);

    k_recur<<<NBLK, 256>>>(wu0, wr0, wc0, wu1, bu1, wr1, br1, wc1, bc1);

    k_logits<<<dim3(158, Tq), 256>>>(ow, ob, out);

    if (out_size >= (int)((size_t)Tq * 128 * VOCq + 2 * BH)) {
        k_hidden<<<128, 512>>>(out + (size_t)Tq * 128 * VOCq);
    }
}

// round 11
// speedup vs baseline: 1.3720x; 1.3720x over previous
#include <cuda_runtime.h>
#include <cuda_bf16.h>

typedef unsigned long long ull;

#define NBLK 128
#define BH   65536
#define Tq   40
#define VOCq 10000

__device__ float g_P[3][Tq * BH];
__device__ float g_C[3][BH];
__device__ float g_H0B[2][BH];
__device__ float g_H1[BH];
__device__ float g_Z0[BH];
__device__ float g_RH0[BH];
__device__ float g_Z1[BH];
__device__ float g_RH1[BH];
__device__ float g_H1seq[Tq * BH];
__device__ unsigned g_cnt;

__device__ __forceinline__ ull pk2(float x, float y) {
    ull r; asm("mov.b64 %0, {%1,%2};" : "=l"(r) : "f"(x), "f"(y)); return r;
}
__device__ __forceinline__ void upk2(ull v, float &x, float &y) {
    asm("mov.b64 {%0,%1}, %2;" : "=f"(x), "=f"(y) : "l"(v));
}
__device__ __forceinline__ void fma2(ull &c, ull a, ull b) {
    asm("fma.rn.f32x2 %0, %1, %2, %3;" : "=l"(c) : "l"(a), "l"(b), "l"(c));
}

__device__ __forceinline__ void gridbar(unsigned &target) {
    __syncthreads();
    target += NBLK;
    if (threadIdx.x == 0) {
        asm volatile("red.release.gpu.add.u32 [%0], %1;" :: "l"(&g_cnt), "r"(1u) : "memory");
        unsigned v, ns = 64;
        while (true) {
            asm volatile("ld.acquire.gpu.u32 %0, [%1];" : "=r"(v) : "l"(&g_cnt) : "memory");
            if ((int)(v - target) >= 0) break;
            __nanosleep(ns);
            if (ns < 256) ns <<= 1;
        }
    }
    __syncthreads();
}

// ---------------- recurrence tile (R9 form — best known) ----------------
template<int BM>
__device__ __noinline__ void gtile(float *sA, float *sW, int m0, int n0, int K,
    const float *A1, const float *A2, const float *W,
    const float *addRow, const float *addMat, int mode,
    const float *mulS, const float *hPrev, const float *zG,
    float *dst, float *dst2)
{
    constexpr int BK = 32, BN = 64, TM = BM / 8, AS = 2 * BM + 4;
    constexpr int ALD = BM * BK / 256;
    const int tid = threadIdx.x, tx = tid & 31, ty = tid >> 5;

    __syncthreads();

    ull acc[TM];
#pragma unroll
    for (int i = 0; i < TM; i++) acc[i] = 0ull;

    auto ald = [&](int kb, int j) -> float {
        int idx = tid + j * 256;
        int k = kb + (idx & 31), m = m0 + (idx >> 5);
        const float *b = (k < 512) ? A1 : A2;
        return b[m * 512 + (k & 511)];
    };

    float ra[ALD]; float4 rw[2];
#pragma unroll
    for (int j = 0; j < ALD; j++) ra[j] = ald(0, j);
#pragma unroll
    for (int j = 0; j < 2; j++) {
        int q = tid + j * 256;
        rw[j] = *(const float4 *)(W + (size_t)(q >> 4) * 512 + n0 + (q & 15) * 4);
    }
#pragma unroll
    for (int j = 0; j < ALD; j++) {
        int idx = tid + j * 256;
        *(ull *)(sA + (idx & 31) * AS + 2 * (idx >> 5)) = pk2(ra[j], ra[j]);
    }
#pragma unroll
    for (int j = 0; j < 2; j++) {
        int q = tid + j * 256;
        *(float4 *)(sW + (q >> 4) * 64 + (q & 15) * 4) = rw[j];
    }
    __syncthreads();

    const int niter = K >> 5;
    for (int it = 0; it < niter; ++it) {
        if (it + 1 < niter) {
            int kb = (it + 1) << 5;
#pragma unroll
            for (int j = 0; j < ALD; j++) ra[j] = ald(kb, j);
#pragma unroll
            for (int j = 0; j < 2; j++) {
                int q = tid + j * 256;
                rw[j] = *(const float4 *)(W + (size_t)(kb + (q >> 4)) * 512 + n0 + (q & 15) * 4);
            }
        }
        const float *A0 = sA + (it & 1) * BK * AS;
        const float *W0 = sW + (it & 1) * BK * BN;
#pragma unroll
        for (int kk = 0; kk < BK; kk++) {
            ull au[TM];
            const ulonglong2 *ap = (const ulonglong2 *)(A0 + kk * AS + 2 * ty * TM);
#pragma unroll
            for (int i = 0; i < TM / 2; i++) {
                ulonglong2 v = ap[i]; au[2 * i] = v.x; au[2 * i + 1] = v.y;
            }
            ull wv = *(const ull *)(W0 + kk * BN + tx * 2);
#pragma unroll
            for (int i = 0; i < TM; i++) fma2(acc[i], au[i], wv);
        }
        if (it + 1 < niter) {
            float *An = sA + ((it + 1) & 1) * BK * AS;
            float *Wn = sW + ((it + 1) & 1) * BK * BN;
#pragma unroll
            for (int j = 0; j < ALD; j++) {
                int idx = tid + j * 256;
                *(ull *)(An + (idx & 31) * AS + 2 * (idx >> 5)) = pk2(ra[j], ra[j]);
            }
#pragma unroll
            for (int j = 0; j < 2; j++) {
                int q = tid + j * 256;
                *(float4 *)(Wn + (q >> 4) * 64 + (q & 15) * 4) = rw[j];
            }
            __syncthreads();
        }
    }

#pragma unroll
    for (int i = 0; i < TM; i++) {
        float lh[2]; upk2(acc[i], lh[0], lh[1]);
        int row = m0 + ty * TM + i, c0 = n0 + tx * 2;
#pragma unroll
        for (int e = 0; e < 2; e++) {
            int c = c0 + e, idx = row * 512 + c;
            float x = lh[e] + (addRow ? addRow[c] : addMat[idx]);
            if (mode == 0) {
                float s = __fdividef(1.f, 1.f + __expf(-x));
                dst[idx] = mulS ? s * mulS[idx] : s;
            } else {
                float ex = __expf(2.f * x);
                float hh = 1.f - __fdividef(2.f, ex + 1.f);
                float z = zG[idx];
                float hn = z * hPrev[idx] + (1.f - z) * hh;
                dst[idx] = hn;
                if (dst2) dst2[idx] = hn;
            }
        }
    }
}

__global__ __launch_bounds__(256, 2) void k_recur(
    const float *wu0, const float *wr0, const float *wc0,
    const float *wu1, const float *bu1, const float *wr1, const float *br1,
    const float *wc1, const float *bc1)
{
    __shared__ __align__(16) float sA[2 * 32 * 68];
    __shared__ __align__(16) float sW[2 * 32 * 64];
    unsigned target = 0;
    const int b = blockIdx.x;

    auto ZR = [&](int t) {
        if (b < 64) {
            if (t < 0) return;
            int gate = b >> 5, id = b & 31;
            int m0 = (id >> 3) * 32, n0 = (id & 7) * 64;
            gtile<32>(sA, sW, m0, n0, 1024, g_H1, g_H0B[t & 1],
                      gate ? wr1 : wu1, gate ? br1 : bu1, nullptr, 0,
                      gate ? (const float *)g_H1 : nullptr, nullptr, nullptr,
                      gate ? g_RH1 : g_Z1, nullptr);
        } else {
            int tn = t + 1;
            if (tn > 39) return;
            int s = b - 64, gate = s >> 5, id = s & 31;
            int m0 = (id >> 3) * 32, n0 = (id & 7) * 64;
            const float *Hp = g_H0B[t & 1];
            gtile<32>(sA, sW, m0, n0, 512, Hp, Hp,
                      gate ? wr0 : wu0, nullptr, g_P[gate] + (size_t)tn * BH, 0,
                      gate ? Hp : nullptr, nullptr, nullptr,
                      gate ? g_RH0 : g_Z0, nullptr);
        }
    };
    auto HP = [&](int t) {
        if (b < 64) {
            int tp = t - 1;
            if (tp < 0) return;
            int m0 = (b >> 3) * 16, n0 = (b & 7) * 64;
            gtile<16>(sA, sW, m0, n0, 1024, g_RH1, g_H0B[tp & 1], wc1,
                      bc1, nullptr, 1, nullptr, g_H1, g_Z1,
                      g_H1, g_H1seq + (size_t)tp * BH);
        } else {
            if (t > 39) return;
            int s = b - 64, m0 = (s >> 3) * 16, n0 = (s & 7) * 64;
            gtile<16>(sA, sW, m0, n0, 512, g_RH0, g_RH0, wc0,
                      nullptr, g_P[2] + (size_t)t * BH, 1,
                      nullptr, g_H0B[(t - 1) & 1], g_Z0,
                      g_H0B[t & 1], nullptr);
        }
    };

    ZR(-1); gridbar(target);
    for (int t = 0; t < Tq; t++) {
        HP(t); gridbar(target);
        ZR(t); gridbar(target);
    }
    HP(Tq);
}

// ---------------- big parallel FFMA2 core (cnn/embed) ----------------
template<int BM, int BN, int BK, int TM, int TN, int THREADS,
         class AF, class WF, class EF>
__device__ __forceinline__ void core(float *sA, float *sW, int tid,
                                     int K, AF aload, WF wload, EF epi)
{
    constexpr int NT = BN / TN, MT = BM / TM, TN2 = TN / 2;
    constexpr int AS = 2 * BM + 4;
    constexpr int ALD = BM * BK / THREADS, WLD = BK * BN / THREADS;
    static_assert(NT * MT == THREADS, "");
    const int tx = tid % NT, ty = tid / NT;
    __syncthreads();
    ull acc[TM][TN2];
#pragma unroll
    for (int i = 0; i < TM; i++)
#pragma unroll
        for (int j = 0; j < TN2; j++) acc[i][j] = 0ull;
#pragma unroll
    for (int j = 0; j < ALD; j++) {
        int idx = tid + j * THREADS;
        float v = aload(idx % BK, idx / BK);
        *(ull *)(sA + (idx % BK) * AS + 2 * (idx / BK)) = pk2(v, v);
    }
#pragma unroll
    for (int j = 0; j < WLD; j++) {
        int idx = tid + j * THREADS;
        sW[(idx / BN) * BN + idx % BN] = wload(idx / BN, idx % BN);
    }
    __syncthreads();
    const int niter = K / BK;
    for (int it = 0; it < niter; ++it) {
        float ra[ALD], rw[WLD];
        if (it + 1 < niter) {
            const int kb = (it + 1) * BK;
#pragma unroll
            for (int j = 0; j < ALD; j++) {
                int idx = tid + j * THREADS;
                ra[j] = aload(kb + idx % BK, idx / BK);
            }
#pragma unroll
            for (int j = 0; j < WLD; j++) {
                int idx = tid + j * THREADS;
                rw[j] = wload(kb + idx / BN, idx % BN);
            }
        }
        const float *A0 = sA + (it & 1) * BK * AS;
        const float *W0 = sW + (it & 1) * BK * BN;
#pragma unroll
        for (int kk = 0; kk < BK; kk++) {
            ull au[TM];
            const ulonglong2 *ap = (const ulonglong2 *)(A0 + kk * AS + 2 * ty * TM);
#pragma unroll
            for (int i = 0; i < TM / 2; i++) {
                ulonglong2 v = ap[i]; au[2 * i] = v.x; au[2 * i + 1] = v.y;
            }
            ull wv[TN2];
            const ull *wp = (const ull *)(W0 + kk * BN + tx * TN);
#pragma unroll
            for (int j = 0; j < TN2; j++) wv[j] = wp[j];
#pragma unroll
            for (int i = 0; i < TM; i++)
#pragma unroll
                for (int j = 0; j < TN2; j++) fma2(acc[i][j], au[i], wv[j]);
        }
        if (it + 1 < niter) {
            float *An = sA + ((it + 1) & 1) * BK * AS;
            float *Wn = sW + ((it + 1) & 1) * BK * BN;
#pragma unroll
            for (int j = 0; j < ALD; j++) {
                int idx = tid + j * THREADS;
                *(ull *)(An + (idx % BK) * AS + 2 * (idx / BK)) = pk2(ra[j], ra[j]);
            }
#pragma unroll
            for (int j = 0; j < WLD; j++) {
                int idx = tid + j * THREADS;
                Wn[(idx / BN) * BN + idx % BN] = rw[j];
            }
            __syncthreads();
        }
    }
#pragma unroll
    for (int i = 0; i < TM; i++)
#pragma unroll
        for (int j = 0; j < TN2; j++) {
            float lo, hi; upk2(acc[i][j], lo, hi);
            epi(ty * TM + i, tx * TN + 2 * j, lo);
            epi(ty * TM + i, tx * TN + 2 * j + 1, hi);
        }
}

__global__ void k_init() {
    int i = blockIdx.x * blockDim.x + threadIdx.x;
    if (i < BH) { g_H0B[1][i] = 0.f; g_H1[i] = 0.f; }
    if (i == 0) g_cnt = 0u;
}

#define BIG_SA (2 * 16 * 132)
#define BIG_SW (2 * 16 * 128)

__global__ __launch_bounds__(256) void k_cnn(const float *cnn,
    const float *wu, const float *wr, const float *wc,
    const float *bu, const float *br, const float *bc)
{
    __shared__ __align__(16) float sA[BIG_SA];
    __shared__ __align__(16) float sW[BIG_SW];
    int g = blockIdx.z, m0 = (blockIdx.x & 1) * 64, n0 = (blockIdx.x >> 1) * 128;
    const float *W    = (g == 0 ? wu : g == 1 ? wr : wc) + 1024 * 512;
    const float *bias = (g == 0 ? bu : g == 1 ? br : bc);
    float *Cout = g_C[g];
    core<64, 128, 16, 8, 4, 256>(sA, sW, threadIdx.x, 512,
        [&](int k, int m) { return cnn[(m0 + m) * 512 + k]; },
        [&](int k, int n) { return W[k * 512 + n0 + n]; },
        [&](int mi, int nj, float v) {
            Cout[(m0 + mi) * 512 + n0 + nj] = v + bias[n0 + nj]; });
}

__global__ __launch_bounds__(256) void k_embed(const int *tokens, const float *emb,
    const float *wu, const float *wr, const float *wc)
{
    __shared__ __align__(16) float sA[BIG_SA];
    __shared__ __align__(16) float sW[BIG_SW];
    __shared__ int rowtok[128];
    int g = blockIdx.z, t = blockIdx.y;
    int m0 = (blockIdx.x & 1) * 64, n0 = (blockIdx.x >> 1) * 128;
    if (threadIdx.x < 128) rowtok[threadIdx.x] = tokens[threadIdx.x * Tq + t];
    __syncthreads();
    const float *W  = (g == 0 ? wu : g == 1 ? wr : wc) + 512 * 512;
    const float *Cg = g_C[g];
    float *Pg = g_P[g] + (size_t)t * BH;
    core<64, 128, 16, 8, 4, 256>(sA, sW, threadIdx.x, 512,
        [&](int k, int m) { return emb[(size_t)rowtok[m0 + m] * 512 + k]; },
        [&](int k, int n) { return W[k * 512 + n0 + n]; },
        [&](int mi, int nj, float v) {
            int idx = (m0 + mi) * 512 + n0 + nj;
            Pg[idx] = v + Cg[idx];
        });
}

// ================= tensor-core logits (split-bf16 mma.sync) =================
// out[b,t,n] = h1seq[t,b,:] @ ow[:,n] + ob[n]
// block: 128m x 128n, K=512, BK=32, 8 warps (warp: 32m x 64n).
// D = Ahi*Bhi + Ahi*Blo + Alo*Bhi  (~1e-5 rel accuracy)
#define ASTR 40     // A smem row stride in bf16 (32 + 8 pad -> conflict-free ldmatrix)
#define BSTR 136    // B smem row stride in bf16 (128 + 8 pad)

__device__ __forceinline__ unsigned s2u(const void *p) {
    return (unsigned)__cvta_generic_to_shared(p);
}
#define LDMX4(r, addr) \
    asm volatile("ldmatrix.sync.aligned.m8n8.x4.shared.b16 {%0,%1,%2,%3},[%4];" \
        : "=r"((r)[0]), "=r"((r)[1]), "=r"((r)[2]), "=r"((r)[3]) : "r"(addr))
#define LDMX4T(r, addr) \
    asm volatile("ldmatrix.sync.aligned.m8n8.x4.trans.shared.b16 {%0,%1,%2,%3},[%4];" \
        : "=r"((r)[0]), "=r"((r)[1]), "=r"((r)[2]), "=r"((r)[3]) : "r"(addr))
#define MMA16816(d, a, b0, b1) \
    asm volatile("mma.sync.aligned.m16n8k16.row.col.f32.bf16.bf16.f32 " \
        "{%0,%1,%2,%3},{%4,%5,%6,%7},{%8,%9},{%0,%1,%2,%3};" \
        : "+f"((d)[0]), "+f"((d)[1]), "+f"((d)[2]), "+f"((d)[3]) \
        : "r"((a)[0]), "r"((a)[1]), "r"((a)[2]), "r"((a)[3]), "r"(b0), "r"(b1))

__device__ __forceinline__ void bsp(float v, __nv_bfloat16 &h, __nv_bfloat16 &l) {
    h = __float2bfloat16(v);
    l = __float2bfloat16(v - __bfloat162float(h));
}

__global__ __launch_bounds__(256) void k_logits_tc(
    const float * __restrict__ ow, const float * __restrict__ ob,
    float * __restrict__ out)
{
    __shared__ __nv_bfloat16 Ahi[128 * ASTR], Alo[128 * ASTR];
    __shared__ __nv_bfloat16 Bhi[32 * BSTR],  Blo[32 * BSTR];

    const int tid = threadIdx.x, lane = tid & 31, w = tid >> 5;
    const int t = blockIdx.y, n0 = blockIdx.x * 128;
    const int wm = (w & 3) * 32, wn = (w >> 2) * 64;
    const float *A = g_H1seq + (size_t)t * BH;

    float acc[2][8][4];
#pragma unroll
    for (int i = 0; i < 2; i++)
#pragma unroll
        for (int j = 0; j < 8; j++)
#pragma unroll
            for (int q = 0; q < 4; q++) acc[i][j][q] = 0.f;

    const int arow = tid >> 1, aoff = (tid & 1) * 16;
    const int brow = tid & 31, bcof = (tid >> 5) * 16;

    for (int kb = 0; kb < 512; kb += 32) {
        __syncthreads();
        // stage A (128x32 fp32 -> split bf16)
        {
            const float4 *src = (const float4 *)(A + arow * 512 + kb + aoff);
#pragma unroll
            for (int j = 0; j < 4; j++) {
                float4 v = src[j];
                __nv_bfloat16 h0, l0, h1, l1, h2, l2, h3, l3;
                bsp(v.x, h0, l0); bsp(v.y, h1, l1); bsp(v.z, h2, l2); bsp(v.w, h3, l3);
                int o = arow * ASTR + aoff + j * 4;
                *(__nv_bfloat162 *)&Ahi[o]     = __halves2bfloat162(h0, h1);
                *(__nv_bfloat162 *)&Ahi[o + 2] = __halves2bfloat162(h2, h3);
                *(__nv_bfloat162 *)&Alo[o]     = __halves2bfloat162(l0, l1);
                *(__nv_bfloat162 *)&Alo[o + 2] = __halves2bfloat162(l2, l3);
            }
        }
        // stage B (32x128 fp32 slice of ow -> split bf16), zero-pad past VOCq
        {
            int gk = kb + brow;
#pragma unroll
            for (int j = 0; j < 4; j++) {
                int n = n0 + bcof + j * 4;
                float4 v = (n < VOCq) ? *(const float4 *)(ow + (size_t)gk * VOCq + n)
                                      : make_float4(0.f, 0.f, 0.f, 0.f);
                __nv_bfloat16 h0, l0, h1, l1, h2, l2, h3, l3;
                bsp(v.x, h0, l0); bsp(v.y, h1, l1); bsp(v.z, h2, l2); bsp(v.w, h3, l3);
                int o = brow * BSTR + bcof + j * 4;
                *(__nv_bfloat162 *)&Bhi[o]     = __halves2bfloat162(h0, h1);
                *(__nv_bfloat162 *)&Bhi[o + 2] = __halves2bfloat162(h2, h3);
                *(__nv_bfloat162 *)&Blo[o]     = __halves2bfloat162(l0, l1);
                *(__nv_bfloat162 *)&Blo[o + 2] = __halves2bfloat162(l2, l3);
            }
        }
        __syncthreads();

#pragma unroll
        for (int ks = 0; ks < 2; ks++) {
            unsigned ah[2][4], al[2][4];
#pragma unroll
            for (int mi = 0; mi < 2; mi++) {
                int row = wm + mi * 16 + (lane & 15);
                unsigned off = row * (ASTR * 2) + ks * 32 + (lane >> 4) * 16;
                LDMX4(ah[mi], s2u(Ahi) + off);
                LDMX4(al[mi], s2u(Alo) + off);
            }
#pragma unroll
            for (int np = 0; np < 4; np++) {
                int kr = ks * 16 + (lane & 15);
                unsigned off = kr * (BSTR * 2) + (wn + np * 16 + (lane >> 4) * 8) * 2;
                unsigned bh[4], bl[4];
                LDMX4T(bh, s2u(Bhi) + off);
                LDMX4T(bl, s2u(Blo) + off);
#pragma unroll
                for (int mi = 0; mi < 2; mi++) {
                    float *d0 = acc[mi][np * 2], *d1 = acc[mi][np * 2 + 1];
                    MMA16816(d0, ah[mi], bh[0], bh[1]);
                    MMA16816(d0, al[mi], bh[0], bh[1]);
                    MMA16816(d0, ah[mi], bl[0], bl[1]);
                    MMA16816(d1, ah[mi], bh[2], bh[3]);
                    MMA16816(d1, al[mi], bh[2], bh[3]);
                    MMA16816(d1, ah[mi], bl[2], bl[3]);
                }
            }
        }
    }

    // epilogue: d0,d1 -> row, cols c,c+1 ; d2,d3 -> row+8
#pragma unroll
    for (int mi = 0; mi < 2; mi++)
#pragma unroll
        for (int nf = 0; nf < 8; nf++) {
            int row = wm + mi * 16 + (lane >> 2);
            int col = n0 + wn + nf * 8 + 2 * (lane & 3);
            if (col < VOCq) {
                float bb = ob[col], bb1 = (col + 1 < VOCq) ? ob[col + 1] : 0.f;
                size_t b1i = ((size_t)row * Tq + t) * VOCq;
                size_t b2i = ((size_t)(row + 8) * Tq + t) * VOCq;
                out[b1i + col] = acc[mi][nf][0] + bb;
                if (col + 1 < VOCq) out[b1i + col + 1] = acc[mi][nf][1] + bb1;
                out[b2i + col] = acc[mi][nf][2] + bb;
                if (col + 1 < VOCq) out[b2i + col + 1] = acc[mi][nf][3] + bb1;
            }
        }
}

__global__ void k_hidden(float *out)
{
    int i = blockIdx.x * blockDim.x + threadIdx.x;
    if (i < BH) { out[i] = g_H0B[1][i]; out[BH + i] = g_H1[i]; }
}

extern "C" void kernel_launch(void *const *d_in, const int *in_sizes, int n_in,
                              void *d_out, int out_size)
{
    const int   *tokens = (const int *)  d_in[0];
    const float *cnn    = (const float *)d_in[1];
    const float *emb    = (const float *)d_in[2];
    const float *wu0 = (const float *)d_in[3],  *bu0 = (const float *)d_in[4];
    const float *wr0 = (const float *)d_in[5],  *br0 = (const float *)d_in[6];
    const float *wc0 = (const float *)d_in[7],  *bc0 = (const float *)d_in[8];
    const float *wu1 = (const float *)d_in[9],  *bu1 = (const float *)d_in[10];
    const float *wr1 = (const float *)d_in[11], *br1 = (const float *)d_in[12];
    const float *wc1 = (const float *)d_in[13], *bc1 = (const float *)d_in[14];
    const float *ow  = (const float *)d_in[15], *ob  = (const float *)d_in[16];
    float *out = (float *)d_out;

    k_init<<<128, 512>>>();
    k_cnn  <<<dim3(8, 1, 3),  256>>>(cnn, wu0, wr0, wc0, bu0, br0, bc0);
    k_embed<<<dim3(8, Tq, 3), 256>>>(tokens, emb, wu0, wr0, wc0);

    k_recur<<<NBLK, 256>>>(wu0, wr0, wc0, wu1, bu1, wr1, br1, wc1, bc1);

    k_logits_tc<<<dim3(79, Tq), 256>>>(ow, ob, out);

    if (out_size >= (int)((size_t)Tq * 128 * VOCq + 2 * BH)) {
        k_hidden<<<128, 512>>>(out + (size_t)Tq * 128 * VOCq);
    }
}

// round 12
// speedup vs baseline: 2.1061x; 1.5351x over previous
#include <cuda_runtime.h>
#include <cuda_bf16.h>

typedef unsigned long long ull;

#define NBLK 128
#define BH   65536
#define Tq   40
#define VOCq 10000

__device__ float g_P[3][Tq * BH];
__device__ float g_C[3][BH];
__device__ float g_H0B[2][BH];
__device__ float g_H1[BH];
__device__ float g_Z0[BH];
__device__ float g_Z1[BH];
__device__ float g_H1seq[Tq * BH];
__device__ unsigned g_cnt;

// split-bf16 planes for TC recurrence operands
__device__ __nv_bfloat16 g_Wh[6][1024 * 512], g_Wl[6][1024 * 512];
__device__ __nv_bfloat16 g_H1h[BH],  g_H1l[BH];
__device__ __nv_bfloat16 g_H0Bh[2][BH], g_H0Bl[2][BH];
__device__ __nv_bfloat16 g_RH1h[BH], g_RH1l[BH];
__device__ __nv_bfloat16 g_RH0h[BH], g_RH0l[BH];

__device__ __forceinline__ ull pk2(float x, float y) {
    ull r; asm("mov.b64 %0, {%1,%2};" : "=l"(r) : "f"(x), "f"(y)); return r;
}
__device__ __forceinline__ void upk2(ull v, float &x, float &y) {
    asm("mov.b64 {%0,%1}, %2;" : "=f"(x), "=f"(y) : "l"(v));
}
__device__ __forceinline__ void fma2(ull &c, ull a, ull b) {
    asm("fma.rn.f32x2 %0, %1, %2, %3;" : "=l"(c) : "l"(a), "l"(b), "l"(c));
}

__device__ __forceinline__ void gridbar(unsigned &target) {
    __syncthreads();
    target += NBLK;
    if (threadIdx.x == 0) {
        asm volatile("red.release.gpu.add.u32 [%0], %1;" :: "l"(&g_cnt), "r"(1u) : "memory");
        unsigned v, ns = 64;
        while (true) {
            asm volatile("ld.acquire.gpu.u32 %0, [%1];" : "=r"(v) : "l"(&g_cnt) : "memory");
            if ((int)(v - target) >= 0) break;
            __nanosleep(ns);
            if (ns < 256) ns <<= 1;
        }
    }
    __syncthreads();
}

// ---------------- TC primitives ----------------
__device__ __forceinline__ unsigned s2u(const void *p) {
    return (unsigned)__cvta_generic_to_shared(p);
}
#define LDMX4(r, addr) \
    asm volatile("ldmatrix.sync.aligned.m8n8.x4.shared.b16 {%0,%1,%2,%3},[%4];" \
        : "=r"((r)[0]), "=r"((r)[1]), "=r"((r)[2]), "=r"((r)[3]) : "r"(addr))
#define LDMX4T(r, addr) \
    asm volatile("ldmatrix.sync.aligned.m8n8.x4.trans.shared.b16 {%0,%1,%2,%3},[%4];" \
        : "=r"((r)[0]), "=r"((r)[1]), "=r"((r)[2]), "=r"((r)[3]) : "r"(addr))
#define LDMX2T(r, addr) \
    asm volatile("ldmatrix.sync.aligned.m8n8.x2.trans.shared.b16 {%0,%1},[%2];" \
        : "=r"((r)[0]), "=r"((r)[1]) : "r"(addr))
#define MMA16816(d, a, b0, b1) \
    asm volatile("mma.sync.aligned.m16n8k16.row.col.f32.bf16.bf16.f32 " \
        "{%0,%1,%2,%3},{%4,%5,%6,%7},{%8,%9},{%0,%1,%2,%3};" \
        : "+f"((d)[0]), "+f"((d)[1]), "+f"((d)[2]), "+f"((d)[3]) \
        : "r"((a)[0]), "r"((a)[1]), "r"((a)[2]), "r"((a)[3]), "r"(b0), "r"(b1))

__device__ __forceinline__ void bsp(float v, __nv_bfloat16 &h, __nv_bfloat16 &l) {
    h = __float2bfloat16(v);
    l = __float2bfloat16(v - __bfloat162float(h));
}

// ================= TC recurrence tile =================
// BMx64 tile, 256 threads, 8 warps; warp w owns cols [n0+8w, n0+8w+8).
// A = concat(A1,A2) bf16 hi/lo planes; W = bf16 hi/lo [K,512] row-major.
// D = Ah*Bh + Al*Bh + Ah*Bl.  mode 0: sigm(+add) (z->dstF fp32 | r->rh bf16 planes);
// mode 1: GRU tanh update (fp32 dstF/dst2F + bf16 planes).
#define ASTR2 40    // A smem row stride (bf16)
#define BSTR2 72    // B smem row stride (bf16); 144B/16=9 -> conflict-free trans ldmatrix

template<int BM>
__device__ __noinline__ void gtile_tc(
    __nv_bfloat16 *sAh, __nv_bfloat16 *sAl,
    __nv_bfloat16 *sBh, __nv_bfloat16 *sBl,
    int m0, int n0, int K,
    const __nv_bfloat16 *A1h, const __nv_bfloat16 *A1l,
    const __nv_bfloat16 *A2h, const __nv_bfloat16 *A2l,
    const __nv_bfloat16 *Wh, const __nv_bfloat16 *Wl,
    const float *addRow, const float *addMat, int mode,
    const float *mulS, const float *hPrev, const float *zG,
    float *dstF, float *dst2F, __nv_bfloat16 *dstH, __nv_bfloat16 *dstL)
{
    constexpr int MF = BM / 16;
    const int tid = threadIdx.x, lane = tid & 31, w = tid >> 5;

    float acc[MF][4];
#pragma unroll
    for (int i = 0; i < MF; i++)
#pragma unroll
        for (int q = 0; q < 4; q++) acc[i][q] = 0.f;

    const bool aact = (tid < BM * 8);
    const int ar = tid >> 3, akq = (tid & 7) * 4;       // A: row, 4 bf16 per thread
    const int br = tid >> 3, bnq = (tid & 7) * 8;       // B: k-row, 8 bf16 per thread

    ull rah = 0, ral = 0, rbh0, rbh1, rbl0, rbl1;
    auto ldA = [&](int kb) {
        if (!aact) return;
        const __nv_bfloat16 *ph = (kb < 512) ? A1h : A2h;
        const __nv_bfloat16 *pl = (kb < 512) ? A1l : A2l;
        size_t off = (size_t)(m0 + ar) * 512 + ((kb & 511) + akq);
        rah = *(const ull *)(ph + off);
        ral = *(const ull *)(pl + off);
    };
    auto ldB = [&](int kb) {
        size_t off = (size_t)(kb + br) * 512 + n0 + bnq;
        rbh0 = *(const ull *)(Wh + off); rbh1 = *(const ull *)(Wh + off + 4);
        rbl0 = *(const ull *)(Wl + off); rbl1 = *(const ull *)(Wl + off + 4);
    };
    auto stAB = [&]() {
        if (aact) {
            *(ull *)(sAh + ar * ASTR2 + akq) = rah;
            *(ull *)(sAl + ar * ASTR2 + akq) = ral;
        }
        *(ull *)(sBh + br * BSTR2 + bnq)     = rbh0;
        *(ull *)(sBh + br * BSTR2 + bnq + 4) = rbh1;
        *(ull *)(sBl + br * BSTR2 + bnq)     = rbl0;
        *(ull *)(sBl + br * BSTR2 + bnq + 4) = rbl1;
    };
    auto comp = [&]() {
#pragma unroll
        for (int ks = 0; ks < 2; ks++) {
            unsigned ah[MF][4], al[MF][4];
#pragma unroll
            for (int mf = 0; mf < MF; mf++) {
                unsigned off = (mf * 16 + (lane & 15)) * (ASTR2 * 2)
                             + ks * 32 + (lane >> 4) * 16;
                LDMX4(ah[mf], s2u(sAh) + off);
                LDMX4(al[mf], s2u(sAl) + off);
            }
            unsigned bh[2], bl[2];
            unsigned boff = (ks * 16 + (lane & 15)) * (BSTR2 * 2) + (8 * w) * 2;
            LDMX2T(bh, s2u(sBh) + boff);
            LDMX2T(bl, s2u(sBl) + boff);
#pragma unroll
            for (int mf = 0; mf < MF; mf++) {
                MMA16816(acc[mf], ah[mf], bh[0], bh[1]);
                MMA16816(acc[mf], al[mf], bh[0], bh[1]);
                MMA16816(acc[mf], ah[mf], bl[0], bl[1]);
            }
        }
    };

    __syncthreads();                       // smem reuse guard across calls
    ldA(0); ldB(0);
    stAB();
    __syncthreads();

    const int niter = K >> 5;
    for (int it = 0; it < niter; ++it) {
        if (it + 1 < niter) { ldA((it + 1) << 5); ldB((it + 1) << 5); }
        comp();
        if (it + 1 < niter) {
            __syncthreads();
            stAB();
            __syncthreads();
        }
    }

    // epilogue
#pragma unroll
    for (int mf = 0; mf < MF; mf++) {
        int row0 = m0 + mf * 16 + (lane >> 2);
        int col  = n0 + 8 * w + 2 * (lane & 3);
#pragma unroll
        for (int half = 0; half < 2; half++) {
            int row = row0 + half * 8;
#pragma unroll
            for (int e = 0; e < 2; e++) {
                float v = acc[mf][half * 2 + e];
                int c = col + e, idx = row * 512 + c;
                float x = v + (addRow ? addRow[c] : addMat[idx]);
                if (mode == 0) {
                    float s = __fdividef(1.f, 1.f + __expf(-x));
                    if (mulS) {               // reset gate -> rh bf16 planes
                        float rh = s * mulS[idx];
                        __nv_bfloat16 hh, ll; bsp(rh, hh, ll);
                        dstH[idx] = hh; dstL[idx] = ll;
                    } else {
                        dstF[idx] = s;        // update gate fp32
                    }
                } else {
                    float ex = __expf(2.f * x);
                    float hh = 1.f - __fdividef(2.f, ex + 1.f);
                    float z  = zG[idx];
                    float hn = z * hPrev[idx] + (1.f - z) * hh;
                    dstF[idx] = hn;
                    if (dst2F) dst2F[idx] = hn;
                    __nv_bfloat16 bh_, bl_; bsp(hn, bh_, bl_);
                    dstH[idx] = bh_; dstL[idx] = bl_;
                }
            }
        }
    }
}

// ---------------- persistent recurrence (mapping/barriers unchanged) --------
__global__ __launch_bounds__(256, 2) void k_recur(
    const float *bu1, const float *br1, const float *bc1)
{
    __shared__ __align__(16) __nv_bfloat16 sAh[32 * ASTR2], sAl[32 * ASTR2];
    __shared__ __align__(16) __nv_bfloat16 sBh[32 * BSTR2], sBl[32 * BSTR2];
    unsigned target = 0;
    const int b = blockIdx.x;

    auto ZR = [&](int t) {
        if (b < 64) {                                   // ZR1(t), K=1024
            if (t < 0) return;
            int gate = b >> 5, id = b & 31;
            int m0 = (id >> 3) * 32, n0 = (id & 7) * 64;
            gtile_tc<32>(sAh, sAl, sBh, sBl, m0, n0, 1024,
                g_H1h, g_H1l, g_H0Bh[t & 1], g_H0Bl[t & 1],
                g_Wh[3 + gate], g_Wl[3 + gate],
                gate ? br1 : bu1, nullptr, 0,
                gate ? (const float *)g_H1 : nullptr, nullptr, nullptr,
                gate ? nullptr : g_Z1, nullptr,
                gate ? g_RH1h : nullptr, gate ? g_RH1l : nullptr);
        } else {                                        // ZR0(t+1), K=512
            int tn = t + 1;
            if (tn > 39) return;
            int s = b - 64, gate = s >> 5, id = s & 31;
            int m0 = (id >> 3) * 32, n0 = (id & 7) * 64;
            gtile_tc<32>(sAh, sAl, sBh, sBl, m0, n0, 512,
                g_H0Bh[t & 1], g_H0Bl[t & 1], g_H0Bh[t & 1], g_H0Bl[t & 1],
                g_Wh[gate], g_Wl[gate],
                nullptr, g_P[gate] + (size_t)tn * BH, 0,
                gate ? g_H0B[t & 1] : nullptr, nullptr, nullptr,
                gate ? nullptr : g_Z0, nullptr,
                gate ? g_RH0h : nullptr, gate ? g_RH0l : nullptr);
        }
    };
    auto HP = [&](int t) {
        if (b < 64) {                                   // H1(t-1), K=1024
            int tp = t - 1;
            if (tp < 0) return;
            int m0 = (b >> 3) * 16, n0 = (b & 7) * 64;
            gtile_tc<16>(sAh, sAl, sBh, sBl, m0, n0, 1024,
                g_RH1h, g_RH1l, g_H0Bh[tp & 1], g_H0Bl[tp & 1],
                g_Wh[5], g_Wl[5],
                bc1, nullptr, 1,
                nullptr, g_H1, g_Z1,
                g_H1, g_H1seq + (size_t)tp * BH, g_H1h, g_H1l);
        } else {                                        // H0(t), K=512
            if (t > 39) return;
            int s = b - 64, m0 = (s >> 3) * 16, n0 = (s & 7) * 64;
            gtile_tc<16>(sAh, sAl, sBh, sBl, m0, n0, 512,
                g_RH0h, g_RH0l, g_RH0h, g_RH0l,
                g_Wh[2], g_Wl[2],
                nullptr, g_P[2] + (size_t)t * BH, 1,
                nullptr, g_H0B[(t - 1) & 1], g_Z0,
                g_H0B[t & 1], nullptr, g_H0Bh[t & 1], g_H0Bl[t & 1]);
        }
    };

    ZR(-1); gridbar(target);
    for (int t = 0; t < Tq; t++) {
        HP(t); gridbar(target);
        ZR(t); gridbar(target);
    }
    HP(Tq);
}

// ---------------- weight prep: fp32 -> split bf16 planes ----------------
__global__ void k_prep(const float *wu0, const float *wr0, const float *wc0,
                       const float *wu1, const float *wr1, const float *wc1)
{
    int m = blockIdx.y;
    const float *src = (m == 0 ? wu0 : m == 1 ? wr0 : m == 2 ? wc0 :
                        m == 3 ? wu1 : m == 4 ? wr1 : wc1);
    int total = ((m < 3) ? 512 : 1024) * 512;   // h-part = rows 0:512 for layer 0
    for (int idx = blockIdx.x * blockDim.x + threadIdx.x; idx < total;
         idx += gridDim.x * blockDim.x) {
        float v = src[idx];
        __nv_bfloat16 h, l; bsp(v, h, l);
        g_Wh[m][idx] = h; g_Wl[m][idx] = l;
    }
}

__global__ void k_init() {
    int i = blockIdx.x * blockDim.x + threadIdx.x;
    if (i < BH) {
        __nv_bfloat16 z = __float2bfloat16(0.f);
        g_H0B[1][i] = 0.f; g_H1[i] = 0.f;
        g_H0Bh[1][i] = z;  g_H0Bl[1][i] = z;
        g_H1h[i] = z;      g_H1l[i] = z;
    }
    if (i == 0) g_cnt = 0u;
}

// ---------------- big parallel FFMA2 core (cnn/embed, unchanged) ------------
template<int BM, int BN, int BK, int TM, int TN, int THREADS,
         class AF, class WF, class EF>
__device__ __forceinline__ void core(float *sA, float *sW, int tid,
                                     int K, AF aload, WF wload, EF epi)
{
    constexpr int NT = BN / TN, MT = BM / TM, TN2 = TN / 2;
    constexpr int AS = 2 * BM + 4;
    constexpr int ALD = BM * BK / THREADS, WLD = BK * BN / THREADS;
    static_assert(NT * MT == THREADS, "");
    const int tx = tid % NT, ty = tid / NT;
    __syncthreads();
    ull acc[TM][TN2];
#pragma unroll
    for (int i = 0; i < TM; i++)
#pragma unroll
        for (int j = 0; j < TN2; j++) acc[i][j] = 0ull;
#pragma unroll
    for (int j = 0; j < ALD; j++) {
        int idx = tid + j * THREADS;
        float v = aload(idx % BK, idx / BK);
        *(ull *)(sA + (idx % BK) * AS + 2 * (idx / BK)) = pk2(v, v);
    }
#pragma unroll
    for (int j = 0; j < WLD; j++) {
        int idx = tid + j * THREADS;
        sW[(idx / BN) * BN + idx % BN] = wload(idx / BN, idx % BN);
    }
    __syncthreads();
    const int niter = K / BK;
    for (int it = 0; it < niter; ++it) {
        float ra[ALD], rw[WLD];
        if (it + 1 < niter) {
            const int kb = (it + 1) * BK;
#pragma unroll
            for (int j = 0; j < ALD; j++) {
                int idx = tid + j * THREADS;
                ra[j] = aload(kb + idx % BK, idx / BK);
            }
#pragma unroll
            for (int j = 0; j < WLD; j++) {
                int idx = tid + j * THREADS;
                rw[j] = wload(kb + idx / BN, idx % BN);
            }
        }
        const float *A0 = sA + (it & 1) * BK * AS;
        const float *W0 = sW + (it & 1) * BK * BN;
#pragma unroll
        for (int kk = 0; kk < BK; kk++) {
            ull au[TM];
            const ulonglong2 *ap = (const ulonglong2 *)(A0 + kk * AS + 2 * ty * TM);
#pragma unroll
            for (int i = 0; i < TM / 2; i++) {
                ulonglong2 v = ap[i]; au[2 * i] = v.x; au[2 * i + 1] = v.y;
            }
            ull wv[TN2];
            const ull *wp = (const ull *)(W0 + kk * BN + tx * TN);
#pragma unroll
            for (int j = 0; j < TN2; j++) wv[j] = wp[j];
#pragma unroll
            for (int i = 0; i < TM; i++)
#pragma unroll
                for (int j = 0; j < TN2; j++) fma2(acc[i][j], au[i], wv[j]);
        }
        if (it + 1 < niter) {
            float *An = sA + ((it + 1) & 1) * BK * AS;
            float *Wn = sW + ((it + 1) & 1) * BK * BN;
#pragma unroll
            for (int j = 0; j < ALD; j++) {
                int idx = tid + j * THREADS;
                *(ull *)(An + (idx % BK) * AS + 2 * (idx / BK)) = pk2(ra[j], ra[j]);
            }
#pragma unroll
            for (int j = 0; j < WLD; j++) {
                int idx = tid + j * THREADS;
                Wn[(idx / BN) * BN + idx % BN] = rw[j];
            }
            __syncthreads();
        }
    }
#pragma unroll
    for (int i = 0; i < TM; i++)
#pragma unroll
        for (int j = 0; j < TN2; j++) {
            float lo, hi; upk2(acc[i][j], lo, hi);
            epi(ty * TM + i, tx * TN + 2 * j, lo);
            epi(ty * TM + i, tx * TN + 2 * j + 1, hi);
        }
}

#define BIG_SA (2 * 16 * 132)
#define BIG_SW (2 * 16 * 128)

__global__ __launch_bounds__(256) void k_cnn(const float *cnn,
    const float *wu, const float *wr, const float *wc,
    const float *bu, const float *br, const float *bc)
{
    __shared__ __align__(16) float sA[BIG_SA];
    __shared__ __align__(16) float sW[BIG_SW];
    int g = blockIdx.z, m0 = (blockIdx.x & 1) * 64, n0 = (blockIdx.x >> 1) * 128;
    const float *W    = (g == 0 ? wu : g == 1 ? wr : wc) + 1024 * 512;
    const float *bias = (g == 0 ? bu : g == 1 ? br : bc);
    float *Cout = g_C[g];
    core<64, 128, 16, 8, 4, 256>(sA, sW, threadIdx.x, 512,
        [&](int k, int m) { return cnn[(m0 + m) * 512 + k]; },
        [&](int k, int n) { return W[k * 512 + n0 + n]; },
        [&](int mi, int nj, float v) {
            Cout[(m0 + mi) * 512 + n0 + nj] = v + bias[n0 + nj]; });
}

__global__ __launch_bounds__(256) void k_embed(const int *tokens, const float *emb,
    const float *wu, const float *wr, const float *wc)
{
    __shared__ __align__(16) float sA[BIG_SA];
    __shared__ __align__(16) float sW[BIG_SW];
    __shared__ int rowtok[128];
    int g = blockIdx.z, t = blockIdx.y;
    int m0 = (blockIdx.x & 1) * 64, n0 = (blockIdx.x >> 1) * 128;
    if (threadIdx.x < 128) rowtok[threadIdx.x] = tokens[threadIdx.x * Tq + t];
    __syncthreads();
    const float *W  = (g == 0 ? wu : g == 1 ? wr : wc) + 512 * 512;
    const float *Cg = g_C[g];
    float *Pg = g_P[g] + (size_t)t * BH;
    core<64, 128, 16, 8, 4, 256>(sA, sW, threadIdx.x, 512,
        [&](int k, int m) { return emb[(size_t)rowtok[m0 + m] * 512 + k]; },
        [&](int k, int n) { return W[k * 512 + n0 + n]; },
        [&](int mi, int nj, float v) {
            int idx = (m0 + mi) * 512 + n0 + nj;
            Pg[idx] = v + Cg[idx];
        });
}

// ================= tensor-core logits (unchanged from R11) =================
#define ASTR 40
#define BSTR 136

__global__ __launch_bounds__(256) void k_logits_tc(
    const float * __restrict__ ow, const float * __restrict__ ob,
    float * __restrict__ out)
{
    __shared__ __nv_bfloat16 Ahi[128 * ASTR], Alo[128 * ASTR];
    __shared__ __nv_bfloat16 Bhi[32 * BSTR],  Blo[32 * BSTR];

    const int tid = threadIdx.x, lane = tid & 31, w = tid >> 5;
    const int t = blockIdx.y, n0 = blockIdx.x * 128;
    const int wm = (w & 3) * 32, wn = (w >> 2) * 64;
    const float *A = g_H1seq + (size_t)t * BH;

    float acc[2][8][4];
#pragma unroll
    for (int i = 0; i < 2; i++)
#pragma unroll
        for (int j = 0; j < 8; j++)
#pragma unroll
            for (int q = 0; q < 4; q++) acc[i][j][q] = 0.f;

    const int arow = tid >> 1, aoff = (tid & 1) * 16;
    const int brow = tid & 31, bcof = (tid >> 5) * 16;

    for (int kb = 0; kb < 512; kb += 32) {
        __syncthreads();
        {
            const float4 *src = (const float4 *)(A + arow * 512 + kb + aoff);
#pragma unroll
            for (int j = 0; j < 4; j++) {
                float4 v = src[j];
                __nv_bfloat16 h0, l0, h1, l1, h2, l2, h3, l3;
                bsp(v.x, h0, l0); bsp(v.y, h1, l1); bsp(v.z, h2, l2); bsp(v.w, h3, l3);
                int o = arow * ASTR + aoff + j * 4;
                *(__nv_bfloat162 *)&Ahi[o]     = __halves2bfloat162(h0, h1);
                *(__nv_bfloat162 *)&Ahi[o + 2] = __halves2bfloat162(h2, h3);
                *(__nv_bfloat162 *)&Alo[o]     = __halves2bfloat162(l0, l1);
                *(__nv_bfloat162 *)&Alo[o + 2] = __halves2bfloat162(l2, l3);
            }
        }
        {
            int gk = kb + brow;
#pragma unroll
            for (int j = 0; j < 4; j++) {
                int n = n0 + bcof + j * 4;
                float4 v = (n < VOCq) ? *(const float4 *)(ow + (size_t)gk * VOCq + n)
                                      : make_float4(0.f, 0.f, 0.f, 0.f);
                __nv_bfloat16 h0, l0, h1, l1, h2, l2, h3, l3;
                bsp(v.x, h0, l0); bsp(v.y, h1, l1); bsp(v.z, h2, l2); bsp(v.w, h3, l3);
                int o = brow * BSTR + bcof + j * 4;
                *(__nv_bfloat162 *)&Bhi[o]     = __halves2bfloat162(h0, h1);
                *(__nv_bfloat162 *)&Bhi[o + 2] = __halves2bfloat162(h2, h3);
                *(__nv_bfloat162 *)&Blo[o]     = __halves2bfloat162(l0, l1);
                *(__nv_bfloat162 *)&Blo[o + 2] = __halves2bfloat162(l2, l3);
            }
        }
        __syncthreads();

#pragma unroll
        for (int ks = 0; ks < 2; ks++) {
            unsigned ah[2][4], al[2][4];
#pragma unroll
            for (int mi = 0; mi < 2; mi++) {
                int row = wm + mi * 16 + (lane & 15);
                unsigned off = row * (ASTR * 2) + ks * 32 + (lane >> 4) * 16;
                LDMX4(ah[mi], s2u(Ahi) + off);
                LDMX4(al[mi], s2u(Alo) + off);
            }
#pragma unroll
            for (int np = 0; np < 4; np++) {
                int kr = ks * 16 + (lane & 15);
                unsigned off = kr * (BSTR * 2) + (wn + np * 16 + (lane >> 4) * 8) * 2;
                unsigned bh[4], bl[4];
                LDMX4T(bh, s2u(Bhi) + off);
                LDMX4T(bl, s2u(Blo) + off);
#pragma unroll
                for (int mi = 0; mi < 2; mi++) {
                    float *d0 = acc[mi][np * 2], *d1 = acc[mi][np * 2 + 1];
                    MMA16816(d0, ah[mi], bh[0], bh[1]);
                    MMA16816(d0, al[mi], bh[0], bh[1]);
                    MMA16816(d0, ah[mi], bl[0], bl[1]);
                    MMA16816(d1, ah[mi], bh[2], bh[3]);
                    MMA16816(d1, al[mi], bh[2], bh[3]);
                    MMA16816(d1, ah[mi], bl[2], bl[3]);
                }
            }
        }
    }

#pragma unroll
    for (int mi = 0; mi < 2; mi++)
#pragma unroll
        for (int nf = 0; nf < 8; nf++) {
            int row = wm + mi * 16 + (lane >> 2);
            int col = n0 + wn + nf * 8 + 2 * (lane & 3);
            if (col < VOCq) {
                float bb = ob[col], bb1 = (col + 1 < VOCq) ? ob[col + 1] : 0.f;
                size_t b1i = ((size_t)row * Tq + t) * VOCq;
                size_t b2i = ((size_t)(row + 8) * Tq + t) * VOCq;
                out[b1i + col] = acc[mi][nf][0] + bb;
                if (col + 1 < VOCq) out[b1i + col + 1] = acc[mi][nf][1] + bb1;
                out[b2i + col] = acc[mi][nf][2] + bb;
                if (col + 1 < VOCq) out[b2i + col + 1] = acc[mi][nf][3] + bb1;
            }
        }
}

__global__ void k_hidden(float *out)
{
    int i = blockIdx.x * blockDim.x + threadIdx.x;
    if (i < BH) { out[i] = g_H0B[1][i]; out[BH + i] = g_H1[i]; }
}

extern "C" void kernel_launch(void *const *d_in, const int *in_sizes, int n_in,
                              void *d_out, int out_size)
{
    const int   *tokens = (const int *)  d_in[0];
    const float *cnn    = (const float *)d_in[1];
    const float *emb    = (const float *)d_in[2];
    const float *wu0 = (const float *)d_in[3],  *bu0 = (const float *)d_in[4];
    const float *wr0 = (const float *)d_in[5],  *br0 = (const float *)d_in[6];
    const float *wc0 = (const float *)d_in[7],  *bc0 = (const float *)d_in[8];
    const float *wu1 = (const float *)d_in[9],  *bu1 = (const float *)d_in[10];
    const float *wr1 = (const float *)d_in[11], *br1 = (const float *)d_in[12];
    const float *wc1 = (const float *)d_in[13], *bc1 = (const float *)d_in[14];
    const float *ow  = (const float *)d_in[15], *ob  = (const float *)d_in[16];
    float *out = (float *)d_out;

    k_init<<<128, 512>>>();
    k_prep<<<dim3(256, 6), 256>>>(wu0, wr0, wc0, wu1, wr1, wc1);
    k_cnn  <<<dim3(8, 1, 3),  256>>>(cnn, wu0, wr0, wc0, bu0, br0, bc0);
    k_embed<<<dim3(8, Tq, 3), 256>>>(tokens, emb, wu0, wr0, wc0);

    k_recur<<<NBLK, 256>>>(bu1, br1, bc1);

    k_logits_tc<<<dim3(79, Tq), 256>>>(ow, ob, out);

    if (out_size >= (int)((size_t)Tq * 128 * VOCq + 2 * BH)) {
        k_hidden<<<128, 512>>>(out + (size_t)Tq * 128 * VOCq);
    }
}

// round 13
// speedup vs baseline: 2.1379x; 1.0151x over previous
#include <cuda_runtime.h>
#include <cuda_bf16.h>

typedef unsigned long long ull;

#define NBLK 128
#define BH   65536
#define Tq   40
#define VOCq 10000

__device__ float g_P[3][Tq * BH];
__device__ float g_C[3][BH];
__device__ float g_H0B[2][BH];
__device__ float g_H1[BH];
__device__ float g_Z0[BH];
__device__ float g_Z1[BH];
__device__ float g_H1seq[Tq * BH];
__device__ unsigned g_cnt;

// split-bf16 planes: weights (rows 0:1024 of each matrix) + states
__device__ __nv_bfloat16 g_Wh[6][1024 * 512], g_Wl[6][1024 * 512];
__device__ __nv_bfloat16 g_H1h[BH],  g_H1l[BH];
__device__ __nv_bfloat16 g_H0Bh[2][BH], g_H0Bl[2][BH];
__device__ __nv_bfloat16 g_RH1h[BH], g_RH1l[BH];
__device__ __nv_bfloat16 g_RH0h[BH], g_RH0l[BH];

__device__ __forceinline__ ull pk2(float x, float y) {
    ull r; asm("mov.b64 %0, {%1,%2};" : "=l"(r) : "f"(x), "f"(y)); return r;
}
__device__ __forceinline__ void upk2(ull v, float &x, float &y) {
    asm("mov.b64 {%0,%1}, %2;" : "=f"(x), "=f"(y) : "l"(v));
}
__device__ __forceinline__ void fma2(ull &c, ull a, ull b) {
    asm("fma.rn.f32x2 %0, %1, %2, %3;" : "=l"(c) : "l"(a), "l"(b), "l"(c));
}

__device__ __forceinline__ void gridbar(unsigned &target) {
    __syncthreads();
    target += NBLK;
    if (threadIdx.x == 0) {
        asm volatile("red.release.gpu.add.u32 [%0], %1;" :: "l"(&g_cnt), "r"(1u) : "memory");
        unsigned v, ns = 64;
        while (true) {
            asm volatile("ld.acquire.gpu.u32 %0, [%1];" : "=r"(v) : "l"(&g_cnt) : "memory");
            if ((int)(v - target) >= 0) break;
            __nanosleep(ns);
            if (ns < 256) ns <<= 1;
        }
    }
    __syncthreads();
}

// ---------------- TC primitives ----------------
__device__ __forceinline__ unsigned s2u(const void *p) {
    return (unsigned)__cvta_generic_to_shared(p);
}
#define LDMX4(r, addr) \
    asm volatile("ldmatrix.sync.aligned.m8n8.x4.shared.b16 {%0,%1,%2,%3},[%4];" \
        : "=r"((r)[0]), "=r"((r)[1]), "=r"((r)[2]), "=r"((r)[3]) : "r"(addr))
#define LDMX4T(r, addr) \
    asm volatile("ldmatrix.sync.aligned.m8n8.x4.trans.shared.b16 {%0,%1,%2,%3},[%4];" \
        : "=r"((r)[0]), "=r"((r)[1]), "=r"((r)[2]), "=r"((r)[3]) : "r"(addr))
#define LDMX2T(r, addr) \
    asm volatile("ldmatrix.sync.aligned.m8n8.x2.trans.shared.b16 {%0,%1},[%2];" \
        : "=r"((r)[0]), "=r"((r)[1]) : "r"(addr))
#define MMA16816(d, a, b0, b1) \
    asm volatile("mma.sync.aligned.m16n8k16.row.col.f32.bf16.bf16.f32 " \
        "{%0,%1,%2,%3},{%4,%5,%6,%7},{%8,%9},{%0,%1,%2,%3};" \
        : "+f"((d)[0]), "+f"((d)[1]), "+f"((d)[2]), "+f"((d)[3]) \
        : "r"((a)[0]), "r"((a)[1]), "r"((a)[2]), "r"((a)[3]), "r"(b0), "r"(b1))

__device__ __forceinline__ void bsp(float v, __nv_bfloat16 &h, __nv_bfloat16 &l) {
    h = __float2bfloat16(v);
    l = __float2bfloat16(v - __bfloat162float(h));
}

// ================= TC recurrence tile (double-buffered) =================
#define ASTR2 40
#define BSTR2 72
#define ABUF (32 * ASTR2)
#define BBUF (32 * BSTR2)

template<int BM>
__device__ __noinline__ void gtile_tc(
    __nv_bfloat16 *sAh, __nv_bfloat16 *sAl,
    __nv_bfloat16 *sBh, __nv_bfloat16 *sBl,
    int m0, int n0, int K,
    const __nv_bfloat16 *A1h, const __nv_bfloat16 *A1l,
    const __nv_bfloat16 *A2h, const __nv_bfloat16 *A2l,
    const __nv_bfloat16 *Wh, const __nv_bfloat16 *Wl,
    const float *addRow, const float *addMat, int mode,
    const float *mulS, const float *hPrev, const float *zG,
    float *dstF, float *dst2F, __nv_bfloat16 *dstH, __nv_bfloat16 *dstL)
{
    constexpr int MF = BM / 16;
    const int tid = threadIdx.x, lane = tid & 31, w = tid >> 5;

    float acc[MF][4];
#pragma unroll
    for (int i = 0; i < MF; i++)
#pragma unroll
        for (int q = 0; q < 4; q++) acc[i][q] = 0.f;

    const bool aact = (tid < BM * 8);
    const int ar = tid >> 3, akq = (tid & 7) * 4;
    const int br = tid >> 3, bnq = (tid & 7) * 8;

    ull rah = 0, ral = 0, rbh0, rbh1, rbl0, rbl1;
    auto ldA = [&](int kb) {
        if (!aact) return;
        const __nv_bfloat16 *ph = (kb < 512) ? A1h : A2h;
        const __nv_bfloat16 *pl = (kb < 512) ? A1l : A2l;
        size_t off = (size_t)(m0 + ar) * 512 + ((kb & 511) + akq);
        rah = *(const ull *)(ph + off);
        ral = *(const ull *)(pl + off);
    };
    auto ldB = [&](int kb) {
        size_t off = (size_t)(kb + br) * 512 + n0 + bnq;
        rbh0 = *(const ull *)(Wh + off); rbh1 = *(const ull *)(Wh + off + 4);
        rbl0 = *(const ull *)(Wl + off); rbl1 = *(const ull *)(Wl + off + 4);
    };
    auto stAB = [&](int buf) {
        if (aact) {
            *(ull *)(sAh + buf * ABUF + ar * ASTR2 + akq) = rah;
            *(ull *)(sAl + buf * ABUF + ar * ASTR2 + akq) = ral;
        }
        __nv_bfloat16 *bh = sBh + buf * BBUF, *bl = sBl + buf * BBUF;
        *(ull *)(bh + br * BSTR2 + bnq)     = rbh0;
        *(ull *)(bh + br * BSTR2 + bnq + 4) = rbh1;
        *(ull *)(bl + br * BSTR2 + bnq)     = rbl0;
        *(ull *)(bl + br * BSTR2 + bnq + 4) = rbl1;
    };
    auto comp = [&](int buf) {
        const __nv_bfloat16 *ah_ = sAh + buf * ABUF, *al_ = sAl + buf * ABUF;
        const __nv_bfloat16 *bh_ = sBh + buf * BBUF, *bl_ = sBl + buf * BBUF;
#pragma unroll
        for (int ks = 0; ks < 2; ks++) {
            unsigned ah[MF][4], al[MF][4];
#pragma unroll
            for (int mf = 0; mf < MF; mf++) {
                unsigned off = (mf * 16 + (lane & 15)) * (ASTR2 * 2)
                             + ks * 32 + (lane >> 4) * 16;
                LDMX4(ah[mf], s2u(ah_) + off);
                LDMX4(al[mf], s2u(al_) + off);
            }
            unsigned bh[2], bl[2];
            unsigned boff = (ks * 16 + (lane & 15)) * (BSTR2 * 2) + (8 * w) * 2;
            LDMX2T(bh, s2u(bh_) + boff);
            LDMX2T(bl, s2u(bl_) + boff);
#pragma unroll
            for (int mf = 0; mf < MF; mf++) {
                MMA16816(acc[mf], ah[mf], bh[0], bh[1]);
                MMA16816(acc[mf], al[mf], bh[0], bh[1]);
                MMA16816(acc[mf], ah[mf], bl[0], bl[1]);
            }
        }
    };

    __syncthreads();                       // smem reuse guard across calls
    ldA(0); ldB(0);
    stAB(0);
    __syncthreads();

    const int niter = K >> 5;
    for (int it = 0; it < niter; ++it) {
        if (it + 1 < niter) { ldA((it + 1) << 5); ldB((it + 1) << 5); }
        comp(it & 1);
        if (it + 1 < niter) {
            stAB((it + 1) & 1);            // other buffer: no conflict with comp
            __syncthreads();
        }
    }

    // epilogue
#pragma unroll
    for (int mf = 0; mf < MF; mf++) {
        int row0 = m0 + mf * 16 + (lane >> 2);
        int col  = n0 + 8 * w + 2 * (lane & 3);
#pragma unroll
        for (int half = 0; half < 2; half++) {
            int row = row0 + half * 8;
#pragma unroll
            for (int e = 0; e < 2; e++) {
                float v = acc[mf][half * 2 + e];
                int c = col + e, idx = row * 512 + c;
                float x = v + (addRow ? addRow[c] : addMat[idx]);
                if (mode == 0) {
                    float s = __fdividef(1.f, 1.f + __expf(-x));
                    if (mulS) {
                        float rh = s * mulS[idx];
                        __nv_bfloat16 hh, ll; bsp(rh, hh, ll);
                        dstH[idx] = hh; dstL[idx] = ll;
                    } else {
                        dstF[idx] = s;
                    }
                } else {
                    float ex = __expf(2.f * x);
                    float hh = 1.f - __fdividef(2.f, ex + 1.f);
                    float z  = zG[idx];
                    float hn = z * hPrev[idx] + (1.f - z) * hh;
                    dstF[idx] = hn;
                    if (dst2F) dst2F[idx] = hn;
                    __nv_bfloat16 bh_, bl_; bsp(hn, bh_, bl_);
                    dstH[idx] = bh_; dstL[idx] = bl_;
                }
            }
        }
    }
}

// ---------------- persistent recurrence ----------------
__global__ __launch_bounds__(256, 2) void k_recur(
    const float *bu1, const float *br1, const float *bc1)
{
    __shared__ __align__(16) __nv_bfloat16 sAh[2 * ABUF], sAl[2 * ABUF];
    __shared__ __align__(16) __nv_bfloat16 sBh[2 * BBUF], sBl[2 * BBUF];
    unsigned target = 0;
    const int b = blockIdx.x;

    auto ZR = [&](int t) {
        if (b < 64) {                                   // ZR1(t), K=1024
            if (t < 0) return;
            int gate = b >> 5, id = b & 31;
            int m0 = (id >> 3) * 32, n0 = (id & 7) * 64;
            gtile_tc<32>(sAh, sAl, sBh, sBl, m0, n0, 1024,
                g_H1h, g_H1l, g_H0Bh[t & 1], g_H0Bl[t & 1],
                g_Wh[3 + gate], g_Wl[3 + gate],
                gate ? br1 : bu1, nullptr, 0,
                gate ? (const float *)g_H1 : nullptr, nullptr, nullptr,
                gate ? nullptr : g_Z1, nullptr,
                gate ? g_RH1h : nullptr, gate ? g_RH1l : nullptr);
        } else {                                        // ZR0(t+1), K=512
            int tn = t + 1;
            if (tn > 39) return;
            int s = b - 64, gate = s >> 5, id = s & 31;
            int m0 = (id >> 3) * 32, n0 = (id & 7) * 64;
            gtile_tc<32>(sAh, sAl, sBh, sBl, m0, n0, 512,
                g_H0Bh[t & 1], g_H0Bl[t & 1], g_H0Bh[t & 1], g_H0Bl[t & 1],
                g_Wh[gate], g_Wl[gate],
                nullptr, g_P[gate] + (size_t)tn * BH, 0,
                gate ? g_H0B[t & 1] : nullptr, nullptr, nullptr,
                gate ? nullptr : g_Z0, nullptr,
                gate ? g_RH0h : nullptr, gate ? g_RH0l : nullptr);
        }
    };
    auto HP = [&](int t) {
        if (b < 64) {                                   // H1(t-1), K=1024
            int tp = t - 1;
            if (tp < 0) return;
            int m0 = (b >> 3) * 16, n0 = (b & 7) * 64;
            gtile_tc<16>(sAh, sAl, sBh, sBl, m0, n0, 1024,
                g_RH1h, g_RH1l, g_H0Bh[tp & 1], g_H0Bl[tp & 1],
                g_Wh[5], g_Wl[5],
                bc1, nullptr, 1,
                nullptr, g_H1, g_Z1,
                g_H1, g_H1seq + (size_t)tp * BH, g_H1h, g_H1l);
        } else {                                        // H0(t), K=512
            if (t > 39) return;
            int s = b - 64, m0 = (s >> 3) * 16, n0 = (s & 7) * 64;
            gtile_tc<16>(sAh, sAl, sBh, sBl, m0, n0, 512,
                g_RH0h, g_RH0l, g_RH0h, g_RH0l,
                g_Wh[2], g_Wl[2],
                nullptr, g_P[2] + (size_t)t * BH, 1,
                nullptr, g_H0B[(t - 1) & 1], g_Z0,
                g_H0B[t & 1], nullptr, g_H0Bh[t & 1], g_H0Bl[t & 1]);
        }
    };

    ZR(-1); gridbar(target);
    for (int t = 0; t < Tq; t++) {
        HP(t); gridbar(target);
        ZR(t); gridbar(target);
    }
    HP(Tq);
}

// ---------------- weight prep: fp32 -> split bf16 planes (rows 0:1024) ------
__global__ void k_prep(const float *wu0, const float *wr0, const float *wc0,
                       const float *wu1, const float *wr1, const float *wc1)
{
    int m = blockIdx.y;
    const float *src = (m == 0 ? wu0 : m == 1 ? wr0 : m == 2 ? wc0 :
                        m == 3 ? wu1 : m == 4 ? wr1 : wc1);
    int total = 1024 * 512;   // layer0: rows 0:512 h-part, 512:1024 x-part
    for (int idx = blockIdx.x * blockDim.x + threadIdx.x; idx < total;
         idx += gridDim.x * blockDim.x) {
        float v = src[idx];
        __nv_bfloat16 h, l; bsp(v, h, l);
        g_Wh[m][idx] = h; g_Wl[m][idx] = l;
    }
}

__global__ void k_init() {
    int i = blockIdx.x * blockDim.x + threadIdx.x;
    if (i < BH) {
        __nv_bfloat16 z = __float2bfloat16(0.f);
        g_H0B[1][i] = 0.f; g_H1[i] = 0.f;
        g_H0Bh[1][i] = z;  g_H0Bl[1][i] = z;
        g_H1h[i] = z;      g_H1l[i] = z;
    }
    if (i == 0) g_cnt = 0u;
}

// ---------------- fp32 FFMA2 core (cnn only) ----------------
template<int BM, int BN, int BK, int TM, int TN, int THREADS,
         class AF, class WF, class EF>
__device__ __forceinline__ void core(float *sA, float *sW, int tid,
                                     int K, AF aload, WF wload, EF epi)
{
    constexpr int NT = BN / TN, MT = BM / TM, TN2 = TN / 2;
    constexpr int AS = 2 * BM + 4;
    constexpr int ALD = BM * BK / THREADS, WLD = BK * BN / THREADS;
    static_assert(NT * MT == THREADS, "");
    const int tx = tid % NT, ty = tid / NT;
    __syncthreads();
    ull acc[TM][TN2];
#pragma unroll
    for (int i = 0; i < TM; i++)
#pragma unroll
        for (int j = 0; j < TN2; j++) acc[i][j] = 0ull;
#pragma unroll
    for (int j = 0; j < ALD; j++) {
        int idx = tid + j * THREADS;
        float v = aload(idx % BK, idx / BK);
        *(ull *)(sA + (idx % BK) * AS + 2 * (idx / BK)) = pk2(v, v);
    }
#pragma unroll
    for (int j = 0; j < WLD; j++) {
        int idx = tid + j * THREADS;
        sW[(idx / BN) * BN + idx % BN] = wload(idx / BN, idx % BN);
    }
    __syncthreads();
    const int niter = K / BK;
    for (int it = 0; it < niter; ++it) {
        float ra[ALD], rw[WLD];
        if (it + 1 < niter) {
            const int kb = (it + 1) * BK;
#pragma unroll
            for (int j = 0; j < ALD; j++) {
                int idx = tid + j * THREADS;
                ra[j] = aload(kb + idx % BK, idx / BK);
            }
#pragma unroll
            for (int j = 0; j < WLD; j++) {
                int idx = tid + j * THREADS;
                rw[j] = wload(kb + idx / BN, idx % BN);
            }
        }
        const float *A0 = sA + (it & 1) * BK * AS;
        const float *W0 = sW + (it & 1) * BK * BN;
#pragma unroll
        for (int kk = 0; kk < BK; kk++) {
            ull au[TM];
            const ulonglong2 *ap = (const ulonglong2 *)(A0 + kk * AS + 2 * ty * TM);
#pragma unroll
            for (int i = 0; i < TM / 2; i++) {
                ulonglong2 v = ap[i]; au[2 * i] = v.x; au[2 * i + 1] = v.y;
            }
            ull wv[TN2];
            const ull *wp = (const ull *)(W0 + kk * BN + tx * TN);
#pragma unroll
            for (int j = 0; j < TN2; j++) wv[j] = wp[j];
#pragma unroll
            for (int i = 0; i < TM; i++)
#pragma unroll
                for (int j = 0; j < TN2; j++) fma2(acc[i][j], au[i], wv[j]);
        }
        if (it + 1 < niter) {
            float *An = sA + ((it + 1) & 1) * BK * AS;
            float *Wn = sW + ((it + 1) & 1) * BK * BN;
#pragma unroll
            for (int j = 0; j < ALD; j++) {
                int idx = tid + j * THREADS;
                *(ull *)(An + (idx % BK) * AS + 2 * (idx / BK)) = pk2(ra[j], ra[j]);
            }
#pragma unroll
            for (int j = 0; j < WLD; j++) {
                int idx = tid + j * THREADS;
                Wn[(idx / BN) * BN + idx % BN] = rw[j];
            }
            __syncthreads();
        }
    }
#pragma unroll
    for (int i = 0; i < TM; i++)
#pragma unroll
        for (int j = 0; j < TN2; j++) {
            float lo, hi; upk2(acc[i][j], lo, hi);
            epi(ty * TM + i, tx * TN + 2 * j, lo);
            epi(ty * TM + i, tx * TN + 2 * j + 1, hi);
        }
}

#define BIG_SA (2 * 16 * 132)
#define BIG_SW (2 * 16 * 128)

__global__ __launch_bounds__(256) void k_cnn(const float *cnn,
    const float *wu, const float *wr, const float *wc,
    const float *bu, const float *br, const float *bc)
{
    __shared__ __align__(16) float sA[BIG_SA];
    __shared__ __align__(16) float sW[BIG_SW];
    int g = blockIdx.z, m0 = (blockIdx.x & 1) * 64, n0 = (blockIdx.x >> 1) * 128;
    const float *W    = (g == 0 ? wu : g == 1 ? wr : wc) + 1024 * 512;
    const float *bias = (g == 0 ? bu : g == 1 ? br : bc);
    float *Cout = g_C[g];
    core<64, 128, 16, 8, 4, 256>(sA, sW, threadIdx.x, 512,
        [&](int k, int m) { return cnn[(m0 + m) * 512 + k]; },
        [&](int k, int n) { return W[k * 512 + n0 + n]; },
        [&](int mi, int nj, float v) {
            Cout[(m0 + mi) * 512 + n0 + nj] = v + bias[n0 + nj]; });
}

// ================= TC embed: P_g[t] = emb[tok] @ W[512:1024] + C_g ==========
#define ASTR 40
#define BSTR 136

__global__ __launch_bounds__(256) void k_embed_tc(
    const int * __restrict__ tokens, const float * __restrict__ emb)
{
    __shared__ __nv_bfloat16 Ahi[128 * ASTR], Alo[128 * ASTR];
    __shared__ __nv_bfloat16 Bhi[32 * BSTR],  Blo[32 * BSTR];
    __shared__ int rowtok[128];

    const int tid = threadIdx.x, lane = tid & 31, w = tid >> 5;
    const int t = blockIdx.y, g = blockIdx.z, n0 = blockIdx.x * 128;
    const int wm = (w & 3) * 32, wn = (w >> 2) * 64;

    if (tid < 128) rowtok[tid] = tokens[tid * Tq + t];
    __syncthreads();

    const __nv_bfloat16 *Wh = g_Wh[g] + 512 * 512;   // x-part rows
    const __nv_bfloat16 *Wl = g_Wl[g] + 512 * 512;
    const float *Cg = g_C[g];
    float *Pg = g_P[g] + (size_t)t * BH;

    float acc[2][8][4];
#pragma unroll
    for (int i = 0; i < 2; i++)
#pragma unroll
        for (int j = 0; j < 8; j++)
#pragma unroll
            for (int q = 0; q < 4; q++) acc[i][j][q] = 0.f;

    const int arow = tid >> 1, aoff = (tid & 1) * 16;
    const int brow = tid & 31, bcof = (tid >> 5) * 16;

    for (int kb = 0; kb < 512; kb += 32) {
        __syncthreads();
        // stage A: gathered emb rows fp32 -> split bf16
        {
            const float4 *src = (const float4 *)(emb + (size_t)rowtok[arow] * 512 + kb + aoff);
#pragma unroll
            for (int j = 0; j < 4; j++) {
                float4 v = src[j];
                __nv_bfloat16 h0, l0, h1, l1, h2, l2, h3, l3;
                bsp(v.x, h0, l0); bsp(v.y, h1, l1); bsp(v.z, h2, l2); bsp(v.w, h3, l3);
                int o = arow * ASTR + aoff + j * 4;
                *(__nv_bfloat162 *)&Ahi[o]     = __halves2bfloat162(h0, h1);
                *(__nv_bfloat162 *)&Ahi[o + 2] = __halves2bfloat162(h2, h3);
                *(__nv_bfloat162 *)&Alo[o]     = __halves2bfloat162(l0, l1);
                *(__nv_bfloat162 *)&Alo[o + 2] = __halves2bfloat162(l2, l3);
            }
        }
        // stage B: already-split weight planes, straight bf16 copy
        {
            size_t off = (size_t)(kb + brow) * 512 + n0 + bcof;
            int o = brow * BSTR + bcof;
            *(ull *)&Bhi[o]     = *(const ull *)(Wh + off);
            *(ull *)&Bhi[o + 4] = *(const ull *)(Wh + off + 4);
            *(ull *)&Bhi[o + 8] = *(const ull *)(Wh + off + 8);
            *(ull *)&Bhi[o + 12]= *(const ull *)(Wh + off + 12);
            *(ull *)&Blo[o]     = *(const ull *)(Wl + off);
            *(ull *)&Blo[o + 4] = *(const ull *)(Wl + off + 4);
            *(ull *)&Blo[o + 8] = *(const ull *)(Wl + off + 8);
            *(ull *)&Blo[o + 12]= *(const ull *)(Wl + off + 12);
        }
        __syncthreads();

#pragma unroll
        for (int ks = 0; ks < 2; ks++) {
            unsigned ah[2][4], al[2][4];
#pragma unroll
            for (int mi = 0; mi < 2; mi++) {
                int row = wm + mi * 16 + (lane & 15);
                unsigned off = row * (ASTR * 2) + ks * 32 + (lane >> 4) * 16;
                LDMX4(ah[mi], s2u(Ahi) + off);
                LDMX4(al[mi], s2u(Alo) + off);
            }
#pragma unroll
            for (int np = 0; np < 4; np++) {
                int kr = ks * 16 + (lane & 15);
                unsigned off = kr * (BSTR * 2) + (wn + np * 16 + (lane >> 4) * 8) * 2;
                unsigned bh[4], bl[4];
                LDMX4T(bh, s2u(Bhi) + off);
                LDMX4T(bl, s2u(Blo) + off);
#pragma unroll
                for (int mi = 0; mi < 2; mi++) {
                    float *d0 = acc[mi][np * 2], *d1 = acc[mi][np * 2 + 1];
                    MMA16816(d0, ah[mi], bh[0], bh[1]);
                    MMA16816(d0, al[mi], bh[0], bh[1]);
                    MMA16816(d0, ah[mi], bl[0], bl[1]);
                    MMA16816(d1, ah[mi], bh[2], bh[3]);
                    MMA16816(d1, al[mi], bh[2], bh[3]);
                    MMA16816(d1, ah[mi], bl[2], bl[3]);
                }
            }
        }
    }

#pragma unroll
    for (int mi = 0; mi < 2; mi++)
#pragma unroll
        for (int nf = 0; nf < 8; nf++) {
            int row = wm + mi * 16 + (lane >> 2);
            int col = n0 + wn + nf * 8 + 2 * (lane & 3);
            int i1 = row * 512 + col, i2 = (row + 8) * 512 + col;
            Pg[i1]     = acc[mi][nf][0] + Cg[i1];
            Pg[i1 + 1] = acc[mi][nf][1] + Cg[i1 + 1];
            Pg[i2]     = acc[mi][nf][2] + Cg[i2];
            Pg[i2 + 1] = acc[mi][nf][3] + Cg[i2 + 1];
        }
}

// ================= tensor-core logits (unchanged) =================
__global__ __launch_bounds__(256) void k_logits_tc(
    const float * __restrict__ ow, const float * __restrict__ ob,
    float * __restrict__ out)
{
    __shared__ __nv_bfloat16 Ahi[128 * ASTR], Alo[128 * ASTR];
    __shared__ __nv_bfloat16 Bhi[32 * BSTR],  Blo[32 * BSTR];

    const int tid = threadIdx.x, lane = tid & 31, w = tid >> 5;
    const int t = blockIdx.y, n0 = blockIdx.x * 128;
    const int wm = (w & 3) * 32, wn = (w >> 2) * 64;
    const float *A = g_H1seq + (size_t)t * BH;

    float acc[2][8][4];
#pragma unroll
    for (int i = 0; i < 2; i++)
#pragma unroll
        for (int j = 0; j < 8; j++)
#pragma unroll
            for (int q = 0; q < 4; q++) acc[i][j][q] = 0.f;

    const int arow = tid >> 1, aoff = (tid & 1) * 16;
    const int brow = tid & 31, bcof = (tid >> 5) * 16;

    for (int kb = 0; kb < 512; kb += 32) {
        __syncthreads();
        {
            const float4 *src = (const float4 *)(A + arow * 512 + kb + aoff);
#pragma unroll
            for (int j = 0; j < 4; j++) {
                float4 v = src[j];
                __nv_bfloat16 h0, l0, h1, l1, h2, l2, h3, l3;
                bsp(v.x, h0, l0); bsp(v.y, h1, l1); bsp(v.z, h2, l2); bsp(v.w, h3, l3);
                int o = arow * ASTR + aoff + j * 4;
                *(__nv_bfloat162 *)&Ahi[o]     = __halves2bfloat162(h0, h1);
                *(__nv_bfloat162 *)&Ahi[o + 2] = __halves2bfloat162(h2, h3);
                *(__nv_bfloat162 *)&Alo[o]     = __halves2bfloat162(l0, l1);
                *(__nv_bfloat162 *)&Alo[o + 2] = __halves2bfloat162(l2, l3);
            }
        }
        {
            int gk = kb + brow;
#pragma unroll
            for (int j = 0; j < 4; j++) {
                int n = n0 + bcof + j * 4;
                float4 v = (n < VOCq) ? *(const float4 *)(ow + (size_t)gk * VOCq + n)
                                      : make_float4(0.f, 0.f, 0.f, 0.f);
                __nv_bfloat16 h0, l0, h1, l1, h2, l2, h3, l3;
                bsp(v.x, h0, l0); bsp(v.y, h1, l1); bsp(v.z, h2, l2); bsp(v.w, h3, l3);
                int o = brow * BSTR + bcof + j * 4;
                *(__nv_bfloat162 *)&Bhi[o]     = __halves2bfloat162(h0, h1);
                *(__nv_bfloat162 *)&Bhi[o + 2] = __halves2bfloat162(h2, h3);
                *(__nv_bfloat162 *)&Blo[o]     = __halves2bfloat162(l0, l1);
                *(__nv_bfloat162 *)&Blo[o + 2] = __halves2bfloat162(l2, l3);
            }
        }
        __syncthreads();

#pragma unroll
        for (int ks = 0; ks < 2; ks++) {
            unsigned ah[2][4], al[2][4];
#pragma unroll
            for (int mi = 0; mi < 2; mi++) {
                int row = wm + mi * 16 + (lane & 15);
                unsigned off = row * (ASTR * 2) + ks * 32 + (lane >> 4) * 16;
                LDMX4(ah[mi], s2u(Ahi) + off);
                LDMX4(al[mi], s2u(Alo) + off);
            }
#pragma unroll
            for (int np = 0; np < 4; np++) {
                int kr = ks * 16 + (lane & 15);
                unsigned off = kr * (BSTR * 2) + (wn + np * 16 + (lane >> 4) * 8) * 2;
                unsigned bh[4], bl[4];
                LDMX4T(bh, s2u(Bhi) + off);
                LDMX4T(bl, s2u(Blo) + off);
#pragma unroll
                for (int mi = 0; mi < 2; mi++) {
                    float *d0 = acc[mi][np * 2], *d1 = acc[mi][np * 2 + 1];
                    MMA16816(d0, ah[mi], bh[0], bh[1]);
                    MMA16816(d0, al[mi], bh[0], bh[1]);
                    MMA16816(d0, ah[mi], bl[0], bl[1]);
                    MMA16816(d1, ah[mi], bh[2], bh[3]);
                    MMA16816(d1, al[mi], bh[2], bh[3]);
                    MMA16816(d1, ah[mi], bl[2], bl[3]);
                }
            }
        }
    }

#pragma unroll
    for (int mi = 0; mi < 2; mi++)
#pragma unroll
        for (int nf = 0; nf < 8; nf++) {
            int row = wm + mi * 16 + (lane >> 2);
            int col = n0 + wn + nf * 8 + 2 * (lane & 3);
            if (col < VOCq) {
                float bb = ob[col], bb1 = (col + 1 < VOCq) ? ob[col + 1] : 0.f;
                size_t b1i = ((size_t)row * Tq + t) * VOCq;
                size_t b2i = ((size_t)(row + 8) * Tq + t) * VOCq;
                out[b1i + col] = acc[mi][nf][0] + bb;
                if (col + 1 < VOCq) out[b1i + col + 1] = acc[mi][nf][1] + bb1;
                out[b2i + col] = acc[mi][nf][2] + bb;
                if (col + 1 < VOCq) out[b2i + col + 1] = acc[mi][nf][3] + bb1;
            }
        }
}

__global__ void k_hidden(float *out)
{
    int i = blockIdx.x * blockDim.x + threadIdx.x;
    if (i < BH) { out[i] = g_H0B[1][i]; out[BH + i] = g_H1[i]; }
}

extern "C" void kernel_launch(void *const *d_in, const int *in_sizes, int n_in,
                              void *d_out, int out_size)
{
    const int   *tokens = (const int *)  d_in[0];
    const float *cnn    = (const float *)d_in[1];
    const float *emb    = (const float *)d_in[2];
    const float *wu0 = (const float *)d_in[3],  *bu0 = (const float *)d_in[4];
    const float *wr0 = (const float *)d_in[5],  *br0 = (const float *)d_in[6];
    const float *wc0 = (const float *)d_in[7],  *bc0 = (const float *)d_in[8];
    const float *wu1 = (const float *)d_in[9],  *bu1 = (const float *)d_in[10];
    const float *wr1 = (const float *)d_in[11], *br1 = (const float *)d_in[12];
    const float *wc1 = (const float *)d_in[13], *bc1 = (const float *)d_in[14];
    const float *ow  = (const float *)d_in[15], *ob  = (const float *)d_in[16];
    float *out = (float *)d_out;

    k_init<<<128, 512>>>();
    k_prep<<<dim3(256, 6), 256>>>(wu0, wr0, wc0, wu1, wr1, wc1);
    k_cnn <<<dim3(8, 1, 3), 256>>>(cnn, wu0, wr0, wc0, bu0, br0, bc0);
    k_embed_tc<<<dim3(4, Tq, 3), 256>>>(tokens, emb);

    k_recur<<<NBLK, 256>>>(bu1, br1, bc1);

    k_logits_tc<<<dim3(79, Tq), 256>>>(ow, ob, out);

    if (out_size >= (int)((size_t)Tq * 128 * VOCq + 2 * BH)) {
        k_hidden<<<128, 512>>>(out + (size_t)Tq * 128 * VOCq);
    }
}

// round 14
// speedup vs baseline: 2.4287x; 1.1360x over previous
#include <cuda_runtime.h>
#include <cuda_bf16.h>

typedef unsigned long long ull;

#define NBLK 128
#define BH   65536
#define Tq   40
#define VOCq 10000

__device__ float g_P[3][Tq * BH];
__device__ float g_C[3][BH];
__device__ float g_H0B[2][BH];
__device__ float g_H1[BH];
__device__ float g_Z0[BH];
__device__ float g_Z1[BH];
__device__ float g_H1seq[Tq * BH];
__device__ unsigned g_cnt;

// split-bf16 planes: weights (rows 0:1024) + states
__device__ __nv_bfloat16 g_Wh[6][1024 * 512], g_Wl[6][1024 * 512];
__device__ __nv_bfloat16 g_H1h[BH],  g_H1l[BH];
__device__ __nv_bfloat16 g_H0Bh[2][BH], g_H0Bl[2][BH];
__device__ __nv_bfloat16 g_RH1h[BH], g_RH1l[BH];
__device__ __nv_bfloat16 g_RH0h[BH], g_RH0l[BH];

__device__ __forceinline__ ull pk2(float x, float y) {
    ull r; asm("mov.b64 %0, {%1,%2};" : "=l"(r) : "f"(x), "f"(y)); return r;
}
__device__ __forceinline__ void upk2(ull v, float &x, float &y) {
    asm("mov.b64 {%0,%1}, %2;" : "=f"(x), "=f"(y) : "l"(v));
}
__device__ __forceinline__ void fma2(ull &c, ull a, ull b) {
    asm("fma.rn.f32x2 %0, %1, %2, %3;" : "=l"(c) : "l"(a), "l"(b), "l"(c));
}

__device__ __forceinline__ void gridbar(unsigned &target) {
    __syncthreads();
    target += NBLK;
    if (threadIdx.x == 0) {
        asm volatile("red.release.gpu.add.u32 [%0], %1;" :: "l"(&g_cnt), "r"(1u) : "memory");
        unsigned v, ns = 64;
        while (true) {
            asm volatile("ld.acquire.gpu.u32 %0, [%1];" : "=r"(v) : "l"(&g_cnt) : "memory");
            if ((int)(v - target) >= 0) break;
            __nanosleep(ns);
            if (ns < 256) ns <<= 1;
        }
    }
    __syncthreads();
}

// ---------------- TC primitives ----------------
__device__ __forceinline__ unsigned s2u(const void *p) {
    return (unsigned)__cvta_generic_to_shared(p);
}
#define LDMX4(r, addr) \
    asm volatile("ldmatrix.sync.aligned.m8n8.x4.shared.b16 {%0,%1,%2,%3},[%4];" \
        : "=r"((r)[0]), "=r"((r)[1]), "=r"((r)[2]), "=r"((r)[3]) : "r"(addr))
#define LDMX4T(r, addr) \
    asm volatile("ldmatrix.sync.aligned.m8n8.x4.trans.shared.b16 {%0,%1,%2,%3},[%4];" \
        : "=r"((r)[0]), "=r"((r)[1]), "=r"((r)[2]), "=r"((r)[3]) : "r"(addr))
#define LDMX2T(r, addr) \
    asm volatile("ldmatrix.sync.aligned.m8n8.x2.trans.shared.b16 {%0,%1},[%2];" \
        : "=r"((r)[0]), "=r"((r)[1]) : "r"(addr))
#define MMA16816(d, a, b0, b1) \
    asm volatile("mma.sync.aligned.m16n8k16.row.col.f32.bf16.bf16.f32 " \
        "{%0,%1,%2,%3},{%4,%5,%6,%7},{%8,%9},{%0,%1,%2,%3};" \
        : "+f"((d)[0]), "+f"((d)[1]), "+f"((d)[2]), "+f"((d)[3]) \
        : "r"((a)[0]), "r"((a)[1]), "r"((a)[2]), "r"((a)[3]), "r"(b0), "r"(b1))

__device__ __forceinline__ void bsp(float v, __nv_bfloat16 &h, __nv_bfloat16 &l) {
    h = __float2bfloat16(v);
    l = __float2bfloat16(v - __bfloat162float(h));
}

__device__ __forceinline__ void cpa16(unsigned dst, const void *src) {
    asm volatile("cp.async.cg.shared.global [%0], [%1], 16;" :: "r"(dst), "l"(src));
}
#define CPA_COMMIT() asm volatile("cp.async.commit_group;" ::: "memory")
#define CPA_WAIT(n)  asm volatile("cp.async.wait_group %0;" :: "n"(n) : "memory")

// ================= TC recurrence tile: 3-stage cp.async pipeline ============
#define ASTR2 40
#define BSTR2 72
#define ABUF (32 * ASTR2)
#define BBUF (32 * BSTR2)

template<int BM>
__device__ __noinline__ void gtile_tc(
    __nv_bfloat16 *sAh, __nv_bfloat16 *sAl,
    __nv_bfloat16 *sBh, __nv_bfloat16 *sBl,
    int m0, int n0, int K,
    const __nv_bfloat16 *A1h, const __nv_bfloat16 *A1l,
    const __nv_bfloat16 *A2h, const __nv_bfloat16 *A2l,
    const __nv_bfloat16 *Wh, const __nv_bfloat16 *Wl,
    const float *addRow, const float *addMat, int mode,
    const float *mulS, const float *hPrev, const float *zG,
    float *dstF, float *dst2F, __nv_bfloat16 *dstH, __nv_bfloat16 *dstL)
{
    constexpr int MF = BM / 16;
    const int tid = threadIdx.x, lane = tid & 31, w = tid >> 5;

    float acc[MF][4];
#pragma unroll
    for (int i = 0; i < MF; i++)
#pragma unroll
        for (int q = 0; q < 4; q++) acc[i][q] = 0.f;

    // cp.async chunk mapping: 16B = 8 bf16 per chunk
    const bool aact = (tid < BM * 4);                  // BM*32*2B/16 chunks
    const int ar = tid >> 2, ak8 = (tid & 3) * 8;      // A: row, k-offset
    const int br = tid >> 3, bn8 = (tid & 7) * 8;      // B: k-row, n-offset

    auto issue = [&](int kb, int buf) {
        if (aact) {
            const __nv_bfloat16 *ph = (kb < 512) ? A1h : A2h;
            const __nv_bfloat16 *pl = (kb < 512) ? A1l : A2l;
            size_t off = (size_t)(m0 + ar) * 512 + ((kb & 511) + ak8);
            unsigned d = buf * ABUF + ar * ASTR2 + ak8;
            cpa16(s2u(sAh) + d * 2, ph + off);
            cpa16(s2u(sAl) + d * 2, pl + off);
        }
        size_t boff = (size_t)(kb + br) * 512 + n0 + bn8;
        unsigned d = buf * BBUF + br * BSTR2 + bn8;
        cpa16(s2u(sBh) + d * 2, Wh + boff);
        cpa16(s2u(sBl) + d * 2, Wl + boff);
    };
    auto comp = [&](int buf) {
        const __nv_bfloat16 *ah_ = sAh + buf * ABUF, *al_ = sAl + buf * ABUF;
        const __nv_bfloat16 *bh_ = sBh + buf * BBUF, *bl_ = sBl + buf * BBUF;
#pragma unroll
        for (int ks = 0; ks < 2; ks++) {
            unsigned ah[MF][4], al[MF][4];
#pragma unroll
            for (int mf = 0; mf < MF; mf++) {
                unsigned off = (mf * 16 + (lane & 15)) * (ASTR2 * 2)
                             + ks * 32 + (lane >> 4) * 16;
                LDMX4(ah[mf], s2u(ah_) + off);
                LDMX4(al[mf], s2u(al_) + off);
            }
            unsigned bh[2], bl[2];
            unsigned boff = (ks * 16 + (lane & 15)) * (BSTR2 * 2) + (8 * w) * 2;
            LDMX2T(bh, s2u(bh_) + boff);
            LDMX2T(bl, s2u(bl_) + boff);
#pragma unroll
            for (int mf = 0; mf < MF; mf++) {
                MMA16816(acc[mf], ah[mf], bh[0], bh[1]);
                MMA16816(acc[mf], al[mf], bh[0], bh[1]);
                MMA16816(acc[mf], ah[mf], bl[0], bl[1]);
            }
        }
    };

    __syncthreads();                   // all threads done with previous call's smem
    const int niter = K >> 5;          // >= 16 always
    issue(0, 0);  CPA_COMMIT();
    issue(32, 1); CPA_COMMIT();

    for (int it = 0; it < niter; ++it) {
        if (it + 2 < niter) CPA_WAIT(1); else CPA_WAIT(0);
        __syncthreads();               // visibility of all threads' copies + buf reuse
        if (it + 2 < niter) {
            issue((it + 2) << 5, (it + 2) % 3);
            CPA_COMMIT();
        }
        comp(it % 3);
    }

    // epilogue
#pragma unroll
    for (int mf = 0; mf < MF; mf++) {
        int row0 = m0 + mf * 16 + (lane >> 2);
        int col  = n0 + 8 * w + 2 * (lane & 3);
#pragma unroll
        for (int half = 0; half < 2; half++) {
            int row = row0 + half * 8;
#pragma unroll
            for (int e = 0; e < 2; e++) {
                float v = acc[mf][half * 2 + e];
                int c = col + e, idx = row * 512 + c;
                float x = v + (addRow ? addRow[c] : addMat[idx]);
                if (mode == 0) {
                    float s = __fdividef(1.f, 1.f + __expf(-x));
                    if (mulS) {
                        float rh = s * mulS[idx];
                        __nv_bfloat16 hh, ll; bsp(rh, hh, ll);
                        dstH[idx] = hh; dstL[idx] = ll;
                    } else {
                        dstF[idx] = s;
                    }
                } else {
                    float ex = __expf(2.f * x);
                    float hh = 1.f - __fdividef(2.f, ex + 1.f);
                    float z  = zG[idx];
                    float hn = z * hPrev[idx] + (1.f - z) * hh;
                    dstF[idx] = hn;
                    if (dst2F) dst2F[idx] = hn;
                    __nv_bfloat16 bh_, bl_; bsp(hn, bh_, bl_);
                    dstH[idx] = bh_; dstL[idx] = bl_;
                }
            }
        }
    }
}

// ---------------- persistent recurrence ----------------
__global__ __launch_bounds__(256, 2) void k_recur(
    const float *bu1, const float *br1, const float *bc1)
{
    __shared__ __align__(16) __nv_bfloat16 sAh[3 * ABUF], sAl[3 * ABUF];
    __shared__ __align__(16) __nv_bfloat16 sBh[3 * BBUF], sBl[3 * BBUF];
    unsigned target = 0;
    const int b = blockIdx.x;

    auto ZR = [&](int t) {
        if (b < 64) {                                   // ZR1(t), K=1024
            if (t < 0) return;
            int gate = b >> 5, id = b & 31;
            int m0 = (id >> 3) * 32, n0 = (id & 7) * 64;
            gtile_tc<32>(sAh, sAl, sBh, sBl, m0, n0, 1024,
                g_H1h, g_H1l, g_H0Bh[t & 1], g_H0Bl[t & 1],
                g_Wh[3 + gate], g_Wl[3 + gate],
                gate ? br1 : bu1, nullptr, 0,
                gate ? (const float *)g_H1 : nullptr, nullptr, nullptr,
                gate ? nullptr : g_Z1, nullptr,
                gate ? g_RH1h : nullptr, gate ? g_RH1l : nullptr);
        } else {                                        // ZR0(t+1), K=512
            int tn = t + 1;
            if (tn > 39) return;
            int s = b - 64, gate = s >> 5, id = s & 31;
            int m0 = (id >> 3) * 32, n0 = (id & 7) * 64;
            gtile_tc<32>(sAh, sAl, sBh, sBl, m0, n0, 512,
                g_H0Bh[t & 1], g_H0Bl[t & 1], g_H0Bh[t & 1], g_H0Bl[t & 1],
                g_Wh[gate], g_Wl[gate],
                nullptr, g_P[gate] + (size_t)tn * BH, 0,
                gate ? g_H0B[t & 1] : nullptr, nullptr, nullptr,
                gate ? nullptr : g_Z0, nullptr,
                gate ? g_RH0h : nullptr, gate ? g_RH0l : nullptr);
        }
    };
    auto HP = [&](int t) {
        if (b < 64) {                                   // H1(t-1), K=1024
            int tp = t - 1;
            if (tp < 0) return;
            int m0 = (b >> 3) * 16, n0 = (b & 7) * 64;
            gtile_tc<16>(sAh, sAl, sBh, sBl, m0, n0, 1024,
                g_RH1h, g_RH1l, g_H0Bh[tp & 1], g_H0Bl[tp & 1],
                g_Wh[5], g_Wl[5],
                bc1, nullptr, 1,
                nullptr, g_H1, g_Z1,
                g_H1, g_H1seq + (size_t)tp * BH, g_H1h, g_H1l);
        } else {                                        // H0(t), K=512
            if (t > 39) return;
            int s = b - 64, m0 = (s >> 3) * 16, n0 = (s & 7) * 64;
            gtile_tc<16>(sAh, sAl, sBh, sBl, m0, n0, 512,
                g_RH0h, g_RH0l, g_RH0h, g_RH0l,
                g_Wh[2], g_Wl[2],
                nullptr, g_P[2] + (size_t)t * BH, 1,
                nullptr, g_H0B[(t - 1) & 1], g_Z0,
                g_H0B[t & 1], nullptr, g_H0Bh[t & 1], g_H0Bl[t & 1]);
        }
    };

    ZR(-1); gridbar(target);
    for (int t = 0; t < Tq; t++) {
        HP(t); gridbar(target);
        ZR(t); gridbar(target);
    }
    HP(Tq);
}

// ---------------- weight prep ----------------
__global__ void k_prep(const float *wu0, const float *wr0, const float *wc0,
                       const float *wu1, const float *wr1, const float *wc1)
{
    int m = blockIdx.y;
    const float *src = (m == 0 ? wu0 : m == 1 ? wr0 : m == 2 ? wc0 :
                        m == 3 ? wu1 : m == 4 ? wr1 : wc1);
    int total = 1024 * 512;
    for (int idx = blockIdx.x * blockDim.x + threadIdx.x; idx < total;
         idx += gridDim.x * blockDim.x) {
        float v = src[idx];
        __nv_bfloat16 h, l; bsp(v, h, l);
        g_Wh[m][idx] = h; g_Wl[m][idx] = l;
    }
}

__global__ void k_init() {
    int i = blockIdx.x * blockDim.x + threadIdx.x;
    if (i < BH) {
        __nv_bfloat16 z = __float2bfloat16(0.f);
        g_H0B[1][i] = 0.f; g_H1[i] = 0.f;
        g_H0Bh[1][i] = z;  g_H0Bl[1][i] = z;
        g_H1h[i] = z;      g_H1l[i] = z;
    }
    if (i == 0) g_cnt = 0u;
}

// ---------------- fp32 FFMA2 core (cnn only) ----------------
template<int BM, int BN, int BK, int TM, int TN, int THREADS,
         class AF, class WF, class EF>
__device__ __forceinline__ void core(float *sA, float *sW, int tid,
                                     int K, AF aload, WF wload, EF epi)
{
    constexpr int NT = BN / TN, MT = BM / TM, TN2 = TN / 2;
    constexpr int AS = 2 * BM + 4;
    constexpr int ALD = BM * BK / THREADS, WLD = BK * BN / THREADS;
    static_assert(NT * MT == THREADS, "");
    const int tx = tid % NT, ty = tid / NT;
    __syncthreads();
    ull acc[TM][TN2];
#pragma unroll
    for (int i = 0; i < TM; i++)
#pragma unroll
        for (int j = 0; j < TN2; j++) acc[i][j] = 0ull;
#pragma unroll
    for (int j = 0; j < ALD; j++) {
        int idx = tid + j * THREADS;
        float v = aload(idx % BK, idx / BK);
        *(ull *)(sA + (idx % BK) * AS + 2 * (idx / BK)) = pk2(v, v);
    }
#pragma unroll
    for (int j = 0; j < WLD; j++) {
        int idx = tid + j * THREADS;
        sW[(idx / BN) * BN + idx % BN] = wload(idx / BN, idx % BN);
    }
    __syncthreads();
    const int niter = K / BK;
    for (int it = 0; it < niter; ++it) {
        float ra[ALD], rw[WLD];
        if (it + 1 < niter) {
            const int kb = (it + 1) * BK;
#pragma unroll
            for (int j = 0; j < ALD; j++) {
                int idx = tid + j * THREADS;
                ra[j] = aload(kb + idx % BK, idx / BK);
            }
#pragma unroll
            for (int j = 0; j < WLD; j++) {
                int idx = tid + j * THREADS;
                rw[j] = wload(kb + idx / BN, idx % BN);
            }
        }
        const float *A0 = sA + (it & 1) * BK * AS;
        const float *W0 = sW + (it & 1) * BK * BN;
#pragma unroll
        for (int kk = 0; kk < BK; kk++) {
            ull au[TM];
            const ulonglong2 *ap = (const ulonglong2 *)(A0 + kk * AS + 2 * ty * TM);
#pragma unroll
            for (int i = 0; i < TM / 2; i++) {
                ulonglong2 v = ap[i]; au[2 * i] = v.x; au[2 * i + 1] = v.y;
            }
            ull wv[TN2];
            const ull *wp = (const ull *)(W0 + kk * BN + tx * TN);
#pragma unroll
            for (int j = 0; j < TN2; j++) wv[j] = wp[j];
#pragma unroll
            for (int i = 0; i < TM; i++)
#pragma unroll
                for (int j = 0; j < TN2; j++) fma2(acc[i][j], au[i], wv[j]);
        }
        if (it + 1 < niter) {
            float *An = sA + ((it + 1) & 1) * BK * AS;
            float *Wn = sW + ((it + 1) & 1) * BK * BN;
#pragma unroll
            for (int j = 0; j < ALD; j++) {
                int idx = tid + j * THREADS;
                *(ull *)(An + (idx % BK) * AS + 2 * (idx / BK)) = pk2(ra[j], ra[j]);
            }
#pragma unroll
            for (int j = 0; j < WLD; j++) {
                int idx = tid + j * THREADS;
                Wn[(idx / BN) * BN + idx % BN] = rw[j];
            }
            __syncthreads();
        }
    }
#pragma unroll
    for (int i = 0; i < TM; i++)
#pragma unroll
        for (int j = 0; j < TN2; j++) {
            float lo, hi; upk2(acc[i][j], lo, hi);
            epi(ty * TM + i, tx * TN + 2 * j, lo);
            epi(ty * TM + i, tx * TN + 2 * j + 1, hi);
        }
}

#define BIG_SA (2 * 16 * 132)
#define BIG_SW (2 * 16 * 128)

__global__ __launch_bounds__(256) void k_cnn(const float *cnn,
    const float *wu, const float *wr, const float *wc,
    const float *bu, const float *br, const float *bc)
{
    __shared__ __align__(16) float sA[BIG_SA];
    __shared__ __align__(16) float sW[BIG_SW];
    int g = blockIdx.z, m0 = (blockIdx.x & 1) * 64, n0 = (blockIdx.x >> 1) * 128;
    const float *W    = (g == 0 ? wu : g == 1 ? wr : wc) + 1024 * 512;
    const float *bias = (g == 0 ? bu : g == 1 ? br : bc);
    float *Cout = g_C[g];
    core<64, 128, 16, 8, 4, 256>(sA, sW, threadIdx.x, 512,
        [&](int k, int m) { return cnn[(m0 + m) * 512 + k]; },
        [&](int k, int n) { return W[k * 512 + n0 + n]; },
        [&](int mi, int nj, float v) {
            Cout[(m0 + mi) * 512 + n0 + nj] = v + bias[n0 + nj]; });
}

// ================= TC embed =================
#define ASTR 40
#define BSTR 136

__global__ __launch_bounds__(256, 2) void k_embed_tc(
    const int * __restrict__ tokens, const float * __restrict__ emb)
{
    __shared__ __nv_bfloat16 Ahi[128 * ASTR], Alo[128 * ASTR];
    __shared__ __nv_bfloat16 Bhi[32 * BSTR],  Blo[32 * BSTR];
    __shared__ int rowtok[128];

    const int tid = threadIdx.x, lane = tid & 31, w = tid >> 5;
    const int t = blockIdx.y, g = blockIdx.z, n0 = blockIdx.x * 128;
    const int wm = (w & 3) * 32, wn = (w >> 2) * 64;

    if (tid < 128) rowtok[tid] = tokens[tid * Tq + t];
    __syncthreads();

    const __nv_bfloat16 *Wh = g_Wh[g] + 512 * 512;
    const __nv_bfloat16 *Wl = g_Wl[g] + 512 * 512;
    const float *Cg = g_C[g];
    float *Pg = g_P[g] + (size_t)t * BH;

    float acc[2][8][4];
#pragma unroll
    for (int i = 0; i < 2; i++)
#pragma unroll
        for (int j = 0; j < 8; j++)
#pragma unroll
            for (int q = 0; q < 4; q++) acc[i][j][q] = 0.f;

    const int arow = tid >> 1, aoff = (tid & 1) * 16;
    const int brow = tid & 31, bcof = (tid >> 5) * 16;

    for (int kb = 0; kb < 512; kb += 32) {
        __syncthreads();
        {
            const float4 *src = (const float4 *)(emb + (size_t)rowtok[arow] * 512 + kb + aoff);
#pragma unroll
            for (int j = 0; j < 4; j++) {
                float4 v = src[j];
                __nv_bfloat16 h0, l0, h1, l1, h2, l2, h3, l3;
                bsp(v.x, h0, l0); bsp(v.y, h1, l1); bsp(v.z, h2, l2); bsp(v.w, h3, l3);
                int o = arow * ASTR + aoff + j * 4;
                *(__nv_bfloat162 *)&Ahi[o]     = __halves2bfloat162(h0, h1);
                *(__nv_bfloat162 *)&Ahi[o + 2] = __halves2bfloat162(h2, h3);
                *(__nv_bfloat162 *)&Alo[o]     = __halves2bfloat162(l0, l1);
                *(__nv_bfloat162 *)&Alo[o + 2] = __halves2bfloat162(l2, l3);
            }
        }
        {
            size_t off = (size_t)(kb + brow) * 512 + n0 + bcof;
            int o = brow * BSTR + bcof;
            *(ull *)&Bhi[o]     = *(const ull *)(Wh + off);
            *(ull *)&Bhi[o + 4] = *(const ull *)(Wh + off + 4);
            *(ull *)&Bhi[o + 8] = *(const ull *)(Wh + off + 8);
            *(ull *)&Bhi[o + 12]= *(const ull *)(Wh + off + 12);
            *(ull *)&Blo[o]     = *(const ull *)(Wl + off);
            *(ull *)&Blo[o + 4] = *(const ull *)(Wl + off + 4);
            *(ull *)&Blo[o + 8] = *(const ull *)(Wl + off + 8);
            *(ull *)&Blo[o + 12]= *(const ull *)(Wl + off + 12);
        }
        __syncthreads();

#pragma unroll
        for (int ks = 0; ks < 2; ks++) {
            unsigned ah[2][4], al[2][4];
#pragma unroll
            for (int mi = 0; mi < 2; mi++) {
                int row = wm + mi * 16 + (lane & 15);
                unsigned off = row * (ASTR * 2) + ks * 32 + (lane >> 4) * 16;
                LDMX4(ah[mi], s2u(Ahi) + off);
                LDMX4(al[mi], s2u(Alo) + off);
            }
#pragma unroll
            for (int np = 0; np < 4; np++) {
                int kr = ks * 16 + (lane & 15);
                unsigned off = kr * (BSTR * 2) + (wn + np * 16 + (lane >> 4) * 8) * 2;
                unsigned bh[4], bl[4];
                LDMX4T(bh, s2u(Bhi) + off);
                LDMX4T(bl, s2u(Blo) + off);
#pragma unroll
                for (int mi = 0; mi < 2; mi++) {
                    float *d0 = acc[mi][np * 2], *d1 = acc[mi][np * 2 + 1];
                    MMA16816(d0, ah[mi], bh[0], bh[1]);
                    MMA16816(d0, al[mi], bh[0], bh[1]);
                    MMA16816(d0, ah[mi], bl[0], bl[1]);
                    MMA16816(d1, ah[mi], bh[2], bh[3]);
                    MMA16816(d1, al[mi], bh[2], bh[3]);
                    MMA16816(d1, ah[mi], bl[2], bl[3]);
                }
            }
        }
    }

#pragma unroll
    for (int mi = 0; mi < 2; mi++)
#pragma unroll
        for (int nf = 0; nf < 8; nf++) {
            int row = wm + mi * 16 + (lane >> 2);
            int col = n0 + wn + nf * 8 + 2 * (lane & 3);
            int i1 = row * 512 + col, i2 = (row + 8) * 512 + col;
            Pg[i1]     = acc[mi][nf][0] + Cg[i1];
            Pg[i1 + 1] = acc[mi][nf][1] + Cg[i1 + 1];
            Pg[i2]     = acc[mi][nf][2] + Cg[i2];
            Pg[i2 + 1] = acc[mi][nf][3] + Cg[i2 + 1];
        }
}

// ================= tensor-core logits =================
__global__ __launch_bounds__(256, 2) void k_logits_tc(
    const float * __restrict__ ow, const float * __restrict__ ob,
    float * __restrict__ out)
{
    __shared__ __nv_bfloat16 Ahi[128 * ASTR], Alo[128 * ASTR];
    __shared__ __nv_bfloat16 Bhi[32 * BSTR],  Blo[32 * BSTR];

    const int tid = threadIdx.x, lane = tid & 31, w = tid >> 5;
    const int t = blockIdx.y, n0 = blockIdx.x * 128;
    const int wm = (w & 3) * 32, wn = (w >> 2) * 64;
    const float *A = g_H1seq + (size_t)t * BH;

    float acc[2][8][4];
#pragma unroll
    for (int i = 0; i < 2; i++)
#pragma unroll
        for (int j = 0; j < 8; j++)
#pragma unroll
            for (int q = 0; q < 4; q++) acc[i][j][q] = 0.f;

    const int arow = tid >> 1, aoff = (tid & 1) * 16;
    const int brow = tid & 31, bcof = (tid >> 5) * 16;

    for (int kb = 0; kb < 512; kb += 32) {
        __syncthreads();
        {
            const float4 *src = (const float4 *)(A + arow * 512 + kb + aoff);
#pragma unroll
            for (int j = 0; j < 4; j++) {
                float4 v = src[j];
                __nv_bfloat16 h0, l0, h1, l1, h2, l2, h3, l3;
                bsp(v.x, h0, l0); bsp(v.y, h1, l1); bsp(v.z, h2, l2); bsp(v.w, h3, l3);
                int o = arow * ASTR + aoff + j * 4;
                *(__nv_bfloat162 *)&Ahi[o]     = __halves2bfloat162(h0, h1);
                *(__nv_bfloat162 *)&Ahi[o + 2] = __halves2bfloat162(h2, h3);
                *(__nv_bfloat162 *)&Alo[o]     = __halves2bfloat162(l0, l1);
                *(__nv_bfloat162 *)&Alo[o + 2] = __halves2bfloat162(l2, l3);
            }
        }
        {
            int gk = kb + brow;
#pragma unroll
            for (int j = 0; j < 4; j++) {
                int n = n0 + bcof + j * 4;
                float4 v = (n < VOCq) ? *(const float4 *)(ow + (size_t)gk * VOCq + n)
                                      : make_float4(0.f, 0.f, 0.f, 0.f);
                __nv_bfloat16 h0, l0, h1, l1, h2, l2, h3, l3;
                bsp(v.x, h0, l0); bsp(v.y, h1, l1); bsp(v.z, h2, l2); bsp(v.w, h3, l3);
                int o = brow * BSTR + bcof + j * 4;
                *(__nv_bfloat162 *)&Bhi[o]     = __halves2bfloat162(h0, h1);
                *(__nv_bfloat162 *)&Bhi[o + 2] = __halves2bfloat162(h2, h3);
                *(__nv_bfloat162 *)&Blo[o]     = __halves2bfloat162(l0, l1);
                *(__nv_bfloat162 *)&Blo[o + 2] = __halves2bfloat162(l2, l3);
            }
        }
        __syncthreads();

#pragma unroll
        for (int ks = 0; ks < 2; ks++) {
            unsigned ah[2][4], al[2][4];
#pragma unroll
            for (int mi = 0; mi < 2; mi++) {
                int row = wm + mi * 16 + (lane & 15);
                unsigned off = row * (ASTR * 2) + ks * 32 + (lane >> 4) * 16;
                LDMX4(ah[mi], s2u(Ahi) + off);
                LDMX4(al[mi], s2u(Alo) + off);
            }
#pragma unroll
            for (int np = 0; np < 4; np++) {
                int kr = ks * 16 + (lane & 15);
                unsigned off = kr * (BSTR * 2) + (wn + np * 16 + (lane >> 4) * 8) * 2;
                unsigned bh[4], bl[4];
                LDMX4T(bh, s2u(Bhi) + off);
                LDMX4T(bl, s2u(Blo) + off);
#pragma unroll
                for (int mi = 0; mi < 2; mi++) {
                    float *d0 = acc[mi][np * 2], *d1 = acc[mi][np * 2 + 1];
                    MMA16816(d0, ah[mi], bh[0], bh[1]);
                    MMA16816(d0, al[mi], bh[0], bh[1]);
                    MMA16816(d0, ah[mi], bl[0], bl[1]);
                    MMA16816(d1, ah[mi], bh[2], bh[3]);
                    MMA16816(d1, al[mi], bh[2], bh[3]);
                    MMA16816(d1, ah[mi], bl[2], bl[3]);
                }
            }
        }
    }

#pragma unroll
    for (int mi = 0; mi < 2; mi++)
#pragma unroll
        for (int nf = 0; nf < 8; nf++) {
            int row = wm + mi * 16 + (lane >> 2);
            int col = n0 + wn + nf * 8 + 2 * (lane & 3);
            if (col < VOCq) {
                float bb = ob[col], bb1 = (col + 1 < VOCq) ? ob[col + 1] : 0.f;
                size_t b1i = ((size_t)row * Tq + t) * VOCq;
                size_t b2i = ((size_t)(row + 8) * Tq + t) * VOCq;
                out[b1i + col] = acc[mi][nf][0] + bb;
                if (col + 1 < VOCq) out[b1i + col + 1] = acc[mi][nf][1] + bb1;
                out[b2i + col] = acc[mi][nf][2] + bb;
                if (col + 1 < VOCq) out[b2i + col + 1] = acc[mi][nf][3] + bb1;
            }
        }
}

__global__ void k_hidden(float *out)
{
    int i = blockIdx.x * blockDim.x + threadIdx.x;
    if (i < BH) { out[i] = g_H0B[1][i]; out[BH + i] = g_H1[i]; }
}

extern "C" void kernel_launch(void *const *d_in, const int *in_sizes, int n_in,
                              void *d_out, int out_size)
{
    const int   *tokens = (const int *)  d_in[0];
    const float *cnn    = (const float *)d_in[1];
    const float *emb    = (const float *)d_in[2];
    const float *wu0 = (const float *)d_in[3],  *bu0 = (const float *)d_in[4];
    const float *wr0 = (const float *)d_in[5],  *br0 = (const float *)d_in[6];
    const float *wc0 = (const float *)d_in[7],  *bc0 = (const float *)d_in[8];
    const float *wu1 = (const float *)d_in[9],  *bu1 = (const float *)d_in[10];
    const float *wr1 = (const float *)d_in[11], *br1 = (const float *)d_in[12];
    const float *wc1 = (const float *)d_in[13], *bc1 = (const float *)d_in[14];
    const float *ow  = (const float *)d_in[15], *ob  = (const float *)d_in[16];
    float *out = (float *)d_out;

    k_init<<<128, 512>>>();
    k_prep<<<dim3(256, 6), 256>>>(wu0, wr0, wc0, wu1, wr1, wc1);
    k_cnn <<<dim3(8, 1, 3), 256>>>(cnn, wu0, wr0, wc0, bu0, br0, bc0);
    k_embed_tc<<<dim3(4, Tq, 3), 256>>>(tokens, emb);

    k_recur<<<NBLK, 256>>>(bu1, br1, bc1);

    k_logits_tc<<<dim3(79, Tq), 256>>>(ow, ob, out);

    if (out_size >= (int)((size_t)Tq * 128 * VOCq + 2 * BH)) {
        k_hidden<<<128, 512>>>(out + (size_t)Tq * 128 * VOCq);
    }
}

// round 16
// speedup vs baseline: 2.6627x; 1.0963x over previous
#include <cuda_runtime.h>
#include <cuda_bf16.h>

typedef unsigned long long ull;
typedef __nv_bfloat16 bf16;

#define NBLK 128
#define BH   65536
#define Tq   40
#define VOCq 10000
#define VPAD 10112              // 79*128, padded vocab for plane layout

__device__ float g_P[3][Tq * BH];
__device__ float g_C[3][BH];
__device__ float g_H0B[2][BH];
__device__ float g_H1[BH];
__device__ float g_Z0[BH];
__device__ float g_Z1[BH];
__device__ unsigned g_cnt;

// split-bf16 planes
__device__ bf16 g_Wh[6][1024 * 512], g_Wl[6][1024 * 512];
__device__ bf16 g_H1h[BH],  g_H1l[BH];
__device__ bf16 g_H0Bh[2][BH], g_H0Bl[2][BH];
__device__ bf16 g_RH1h[BH], g_RH1l[BH];
__device__ bf16 g_RH0h[BH], g_RH0l[BH];
__device__ bf16 g_Sh[Tq * BH], g_Sl[Tq * BH];          // h1seq planes
__device__ bf16 g_Eh[Tq * BH], g_El[Tq * BH];          // gathered emb planes
__device__ bf16 g_OWh[512 * VPAD], g_OWl[512 * VPAD];  // out_w planes (padded)

__device__ __forceinline__ ull pk2(float x, float y) {
    ull r; asm("mov.b64 %0, {%1,%2};" : "=l"(r) : "f"(x), "f"(y)); return r;
}
__device__ __forceinline__ void upk2(ull v, float &x, float &y) {
    asm("mov.b64 {%0,%1}, %2;" : "=f"(x), "=f"(y) : "l"(v));
}
__device__ __forceinline__ void fma2(ull &c, ull a, ull b) {
    asm("fma.rn.f32x2 %0, %1, %2, %3;" : "=l"(c) : "l"(a), "l"(b), "l"(c));
}

__device__ __forceinline__ void gridbar(unsigned &target) {
    __syncthreads();
    target += NBLK;
    if (threadIdx.x == 0) {
        asm volatile("red.release.gpu.add.u32 [%0], %1;" :: "l"(&g_cnt), "r"(1u) : "memory");
        unsigned v, ns = 64;
        while (true) {
            asm volatile("ld.acquire.gpu.u32 %0, [%1];" : "=r"(v) : "l"(&g_cnt) : "memory");
            if ((int)(v - target) >= 0) break;
            __nanosleep(ns);
            if (ns < 256) ns <<= 1;
        }
    }
    __syncthreads();
}

// ---------------- TC primitives ----------------
__device__ __forceinline__ unsigned s2u(const void *p) {
    return (unsigned)__cvta_generic_to_shared(p);
}
#define LDMX4(r, addr) \
    asm volatile("ldmatrix.sync.aligned.m8n8.x4.shared.b16 {%0,%1,%2,%3},[%4];" \
        : "=r"((r)[0]), "=r"((r)[1]), "=r"((r)[2]), "=r"((r)[3]) : "r"(addr))
#define LDMX4T(r, addr) \
    asm volatile("ldmatrix.sync.aligned.m8n8.x4.trans.shared.b16 {%0,%1,%2,%3},[%4];" \
        : "=r"((r)[0]), "=r"((r)[1]), "=r"((r)[2]), "=r"((r)[3]) : "r"(addr))
#define LDMX2T(r, addr) \
    asm volatile("ldmatrix.sync.aligned.m8n8.x2.trans.shared.b16 {%0,%1},[%2];" \
        : "=r"((r)[0]), "=r"((r)[1]) : "r"(addr))
#define MMA16816(d, a, b0, b1) \
    asm volatile("mma.sync.aligned.m16n8k16.row.col.f32.bf16.bf16.f32 " \
        "{%0,%1,%2,%3},{%4,%5,%6,%7},{%8,%9},{%0,%1,%2,%3};" \
        : "+f"((d)[0]), "+f"((d)[1]), "+f"((d)[2]), "+f"((d)[3]) \
        : "r"((a)[0]), "r"((a)[1]), "r"((a)[2]), "r"((a)[3]), "r"(b0), "r"(b1))

__device__ __forceinline__ void bsp(float v, bf16 &h, bf16 &l) {
    h = __float2bfloat16(v);
    l = __float2bfloat16(v - __bfloat162float(h));
}

__device__ __forceinline__ void cpa16(unsigned dst, const void *src) {
    asm volatile("cp.async.cg.shared.global [%0], [%1], 16;" :: "r"(dst), "l"(src));
}
#define CPA_COMMIT() asm volatile("cp.async.commit_group;" ::: "memory")
#define CPA_WAIT(n)  asm volatile("cp.async.wait_group %0;" :: "n"(n) : "memory")

// ================= TC recurrence tile: 3-stage cp.async =================
#define ASTR2 40
#define BSTR2 72
#define ABUF (32 * ASTR2)
#define BBUF (32 * BSTR2)

template<int BM>
__device__ __noinline__ void gtile_tc(
    bf16 *sAh, bf16 *sAl, bf16 *sBh, bf16 *sBl,
    int m0, int n0, int K,
    const bf16 *A1h, const bf16 *A1l, const bf16 *A2h, const bf16 *A2l,
    const bf16 *Wh, const bf16 *Wl,
    const float *addRow, const float *addMat, int mode,
    const float *mulS, const float *hPrev, const float *zG,
    float *dstF, bf16 *dstH, bf16 *dstL,
    bf16 *seqH, bf16 *seqL)
{
    constexpr int MF = BM / 16;
    const int tid = threadIdx.x, lane = tid & 31, w = tid >> 5;

    float acc[MF][4];
#pragma unroll
    for (int i = 0; i < MF; i++)
#pragma unroll
        for (int q = 0; q < 4; q++) acc[i][q] = 0.f;

    const bool aact = (tid < BM * 4);
    const int ar = tid >> 2, ak8 = (tid & 3) * 8;
    const int br = tid >> 3, bn8 = (tid & 7) * 8;

    auto issue = [&](int kb, int buf) {
        if (aact) {
            const bf16 *ph = (kb < 512) ? A1h : A2h;
            const bf16 *pl = (kb < 512) ? A1l : A2l;
            size_t off = (size_t)(m0 + ar) * 512 + ((kb & 511) + ak8);
            unsigned d = buf * ABUF + ar * ASTR2 + ak8;
            cpa16(s2u(sAh) + d * 2, ph + off);
            cpa16(s2u(sAl) + d * 2, pl + off);
        }
        size_t boff = (size_t)(kb + br) * 512 + n0 + bn8;
        unsigned d = buf * BBUF + br * BSTR2 + bn8;
        cpa16(s2u(sBh) + d * 2, Wh + boff);
        cpa16(s2u(sBl) + d * 2, Wl + boff);
    };
    auto comp = [&](int buf) {
        const bf16 *ah_ = sAh + buf * ABUF, *al_ = sAl + buf * ABUF;
        const bf16 *bh_ = sBh + buf * BBUF, *bl_ = sBl + buf * BBUF;
#pragma unroll
        for (int ks = 0; ks < 2; ks++) {
            unsigned ah[MF][4], al[MF][4];
#pragma unroll
            for (int mf = 0; mf < MF; mf++) {
                unsigned off = (mf * 16 + (lane & 15)) * (ASTR2 * 2)
                             + ks * 32 + (lane >> 4) * 16;
                LDMX4(ah[mf], s2u(ah_) + off);
                LDMX4(al[mf], s2u(al_) + off);
            }
            unsigned bh[2], bl[2];
            unsigned boff = (ks * 16 + (lane & 15)) * (BSTR2 * 2) + (8 * w) * 2;
            LDMX2T(bh, s2u(bh_) + boff);
            LDMX2T(bl, s2u(bl_) + boff);
#pragma unroll
            for (int mf = 0; mf < MF; mf++) {
                MMA16816(acc[mf], ah[mf], bh[0], bh[1]);
                MMA16816(acc[mf], al[mf], bh[0], bh[1]);
                MMA16816(acc[mf], ah[mf], bl[0], bl[1]);
            }
        }
    };

    __syncthreads();
    const int niter = K >> 5;
    issue(0, 0);  CPA_COMMIT();
    issue(32, 1); CPA_COMMIT();

    for (int it = 0; it < niter; ++it) {
        if (it + 2 < niter) CPA_WAIT(1); else CPA_WAIT(0);
        __syncthreads();
        if (it + 2 < niter) {
            issue((it + 2) << 5, (it + 2) % 3);
            CPA_COMMIT();
        }
        comp(it % 3);
    }

#pragma unroll
    for (int mf = 0; mf < MF; mf++) {
        int row0 = m0 + mf * 16 + (lane >> 2);
        int col  = n0 + 8 * w + 2 * (lane & 3);
#pragma unroll
        for (int half = 0; half < 2; half++) {
            int row = row0 + half * 8;
#pragma unroll
            for (int e = 0; e < 2; e++) {
                float v = acc[mf][half * 2 + e];
                int c = col + e, idx = row * 512 + c;
                float x = v + (addRow ? addRow[c] : addMat[idx]);
                if (mode == 0) {
                    float s = __fdividef(1.f, 1.f + __expf(-x));
                    if (mulS) {
                        float rh = s * mulS[idx];
                        bf16 hh, ll; bsp(rh, hh, ll);
                        dstH[idx] = hh; dstL[idx] = ll;
                    } else {
                        dstF[idx] = s;
                    }
                } else {
                    float ex = __expf(2.f * x);
                    float hh = 1.f - __fdividef(2.f, ex + 1.f);
                    float z  = zG[idx];
                    float hn = z * hPrev[idx] + (1.f - z) * hh;
                    dstF[idx] = hn;
                    bf16 bh_, bl_; bsp(hn, bh_, bl_);
                    dstH[idx] = bh_; dstL[idx] = bl_;
                    if (seqH) { seqH[idx] = bh_; seqL[idx] = bl_; }
                }
            }
        }
    }
}

// ---------------- persistent recurrence ----------------
__global__ __launch_bounds__(256, 2) void k_recur(
    const float *bu1, const float *br1, const float *bc1)
{
    __shared__ __align__(16) bf16 sAh[3 * ABUF], sAl[3 * ABUF];
    __shared__ __align__(16) bf16 sBh[3 * BBUF], sBl[3 * BBUF];
    unsigned target = 0;
    const int b = blockIdx.x;

    auto ZR = [&](int t) {
        if (b < 64) {                                   // ZR1(t), K=1024
            if (t < 0) return;
            int gate = b >> 5, id = b & 31;
            int m0 = (id >> 3) * 32, n0 = (id & 7) * 64;
            gtile_tc<32>(sAh, sAl, sBh, sBl, m0, n0, 1024,
                g_H1h, g_H1l, g_H0Bh[t & 1], g_H0Bl[t & 1],
                g_Wh[3 + gate], g_Wl[3 + gate],
                gate ? br1 : bu1, nullptr, 0,
                gate ? (const float *)g_H1 : nullptr, nullptr, nullptr,
                gate ? nullptr : g_Z1,
                gate ? g_RH1h : nullptr, gate ? g_RH1l : nullptr,
                nullptr, nullptr);
        } else {                                        // ZR0(t+1), K=512
            int tn = t + 1;
            if (tn > 39) return;
            int s = b - 64, gate = s >> 5, id = s & 31;
            int m0 = (id >> 3) * 32, n0 = (id & 7) * 64;
            gtile_tc<32>(sAh, sAl, sBh, sBl, m0, n0, 512,
                g_H0Bh[t & 1], g_H0Bl[t & 1], g_H0Bh[t & 1], g_H0Bl[t & 1],
                g_Wh[gate], g_Wl[gate],
                nullptr, g_P[gate] + (size_t)tn * BH, 0,
                gate ? g_H0B[t & 1] : nullptr, nullptr, nullptr,
                gate ? nullptr : g_Z0,
                gate ? g_RH0h : nullptr, gate ? g_RH0l : nullptr,
                nullptr, nullptr);
        }
    };
    auto HP = [&](int t) {
        if (b < 64) {                                   // H1(t-1), K=1024
            int tp = t - 1;
            if (tp < 0) return;
            int m0 = (b >> 3) * 16, n0 = (b & 7) * 64;
            gtile_tc<16>(sAh, sAl, sBh, sBl, m0, n0, 1024,
                g_RH1h, g_RH1l, g_H0Bh[tp & 1], g_H0Bl[tp & 1],
                g_Wh[5], g_Wl[5],
                bc1, nullptr, 1,
                nullptr, g_H1, g_Z1,
                g_H1, g_H1h, g_H1l,
                g_Sh + (size_t)tp * BH, g_Sl + (size_t)tp * BH);
        } else {                                        // H0(t), K=512
            if (t > 39) return;
            int s = b - 64, m0 = (s >> 3) * 16, n0 = (s & 7) * 64;
            gtile_tc<16>(sAh, sAl, sBh, sBl, m0, n0, 512,
                g_RH0h, g_RH0l, g_RH0h, g_RH0l,
                g_Wh[2], g_Wl[2],
                nullptr, g_P[2] + (size_t)t * BH, 1,
                nullptr, g_H0B[(t - 1) & 1], g_Z0,
                g_H0B[t & 1], g_H0Bh[t & 1], g_H0Bl[t & 1],
                nullptr, nullptr);
        }
    };

    ZR(-1); gridbar(target);
    for (int t = 0; t < Tq; t++) {
        HP(t); gridbar(target);
        ZR(t); gridbar(target);
    }
    HP(Tq);
}

// ---------------- one-time prep kernels ----------------
__global__ void k_prep(const float *wu0, const float *wr0, const float *wc0,
                       const float *wu1, const float *wr1, const float *wc1)
{
    int m = blockIdx.y;
    const float *src = (m == 0 ? wu0 : m == 1 ? wr0 : m == 2 ? wc0 :
                        m == 3 ? wu1 : m == 4 ? wr1 : wc1);
    int total = 1024 * 512;
    for (int idx = blockIdx.x * blockDim.x + threadIdx.x; idx < total;
         idx += gridDim.x * blockDim.x) {
        float v = src[idx];
        bf16 h, l; bsp(v, h, l);
        g_Wh[m][idx] = h; g_Wl[m][idx] = l;
    }
}

__global__ void k_prep_ow(const float *ow)
{
    for (int idx = blockIdx.x * blockDim.x + threadIdx.x; idx < 512 * VPAD;
         idx += gridDim.x * blockDim.x) {
        int k = idx / VPAD, n = idx % VPAD;
        float v = (n < VOCq) ? ow[(size_t)k * VOCq + n] : 0.f;
        bf16 h, l; bsp(v, h, l);
        g_OWh[idx] = h; g_OWl[idx] = l;
    }
}

__global__ void k_eprep(const int *tokens, const float *emb)
{
    for (int idx = blockIdx.x * blockDim.x + threadIdx.x; idx < Tq * BH;
         idx += gridDim.x * blockDim.x) {
        int t = idx / BH, r = (idx / 512) & 127, k = idx & 511;
        float v = emb[(size_t)tokens[r * Tq + t] * 512 + k];
        bf16 h, l; bsp(v, h, l);
        g_Eh[idx] = h; g_El[idx] = l;
    }
}

__global__ void k_init() {
    int i = blockIdx.x * blockDim.x + threadIdx.x;
    if (i < BH) {
        bf16 z = __float2bfloat16(0.f);
        g_H0B[1][i] = 0.f; g_H1[i] = 0.f;
        g_H0Bh[1][i] = z;  g_H0Bl[1][i] = z;
        g_H1h[i] = z;      g_H1l[i] = z;
    }
    if (i == 0) g_cnt = 0u;
}

// ---------------- fp32 FFMA2 core (cnn only) ----------------
template<int BM, int BN, int BK, int TM, int TN, int THREADS,
         class AF, class WF, class EF>
__device__ __forceinline__ void core(float *sA, float *sW, int tid,
                                     int K, AF aload, WF wload, EF epi)
{
    constexpr int NT = BN / TN, MT = BM / TM, TN2 = TN / 2;
    constexpr int AS = 2 * BM + 4;
    constexpr int ALD = BM * BK / THREADS, WLD = BK * BN / THREADS;
    static_assert(NT * MT == THREADS, "");
    const int tx = tid % NT, ty = tid / NT;
    __syncthreads();
    ull acc[TM][TN2];
#pragma unroll
    for (int i = 0; i < TM; i++)
#pragma unroll
        for (int j = 0; j < TN2; j++) acc[i][j] = 0ull;
#pragma unroll
    for (int j = 0; j < ALD; j++) {
        int idx = tid + j * THREADS;
        float v = aload(idx % BK, idx / BK);
        *(ull *)(sA + (idx % BK) * AS + 2 * (idx / BK)) = pk2(v, v);
    }
#pragma unroll
    for (int j = 0; j < WLD; j++) {
        int idx = tid + j * THREADS;
        sW[(idx / BN) * BN + idx % BN] = wload(idx / BN, idx % BN);
    }
    __syncthreads();
    const int niter = K / BK;
    for (int it = 0; it < niter; ++it) {
        float ra[ALD], rw[WLD];
        if (it + 1 < niter) {
            const int kb = (it + 1) * BK;
#pragma unroll
            for (int j = 0; j < ALD; j++) {
                int idx = tid + j * THREADS;
                ra[j] = aload(kb + idx % BK, idx / BK);
            }
#pragma unroll
            for (int j = 0; j < WLD; j++) {
                int idx = tid + j * THREADS;
                rw[j] = wload(kb + idx / BN, idx % BN);
            }
        }
        const float *A0 = sA + (it & 1) * BK * AS;
        const float *W0 = sW + (it & 1) * BK * BN;
#pragma unroll
        for (int kk = 0; kk < BK; kk++) {
            ull au[TM];
            const ulonglong2 *ap = (const ulonglong2 *)(A0 + kk * AS + 2 * ty * TM);
#pragma unroll
            for (int i = 0; i < TM / 2; i++) {
                ulonglong2 v = ap[i]; au[2 * i] = v.x; au[2 * i + 1] = v.y;
            }
            ull wv[TN2];
            const ull *wp = (const ull *)(W0 + kk * BN + tx * TN);
#pragma unroll
            for (int j = 0; j < TN2; j++) wv[j] = wp[j];
#pragma unroll
            for (int i = 0; i < TM; i++)
#pragma unroll
                for (int j = 0; j < TN2; j++) fma2(acc[i][j], au[i], wv[j]);
        }
        if (it + 1 < niter) {
            float *An = sA + ((it + 1) & 1) * BK * AS;
            float *Wn = sW + ((it + 1) & 1) * BK * BN;
#pragma unroll
            for (int j = 0; j < ALD; j++) {
                int idx = tid + j * THREADS;
                *(ull *)(An + (idx % BK) * AS + 2 * (idx / BK)) = pk2(ra[j], ra[j]);
            }
#pragma unroll
            for (int j = 0; j < WLD; j++) {
                int idx = tid + j * THREADS;
                Wn[(idx / BN) * BN + idx % BN] = rw[j];
            }
            __syncthreads();
        }
    }
#pragma unroll
    for (int i = 0; i < TM; i++)
#pragma unroll
        for (int j = 0; j < TN2; j++) {
            float lo, hi; upk2(acc[i][j], lo, hi);
            epi(ty * TM + i, tx * TN + 2 * j, lo);
            epi(ty * TM + i, tx * TN + 2 * j + 1, hi);
        }
}

#define BIG_SA (2 * 16 * 132)
#define BIG_SW (2 * 16 * 128)

__global__ __launch_bounds__(256) void k_cnn(const float *cnn,
    const float *wu, const float *wr, const float *wc,
    const float *bu, const float *br, const float *bc)
{
    __shared__ __align__(16) float sA[BIG_SA];
    __shared__ __align__(16) float sW[BIG_SW];
    int g = blockIdx.z, m0 = (blockIdx.x & 1) * 64, n0 = (blockIdx.x >> 1) * 128;
    const float *W    = (g == 0 ? wu : g == 1 ? wr : wc) + 1024 * 512;
    const float *bias = (g == 0 ? bu : g == 1 ? br : bc);
    float *Cout = g_C[g];
    core<64, 128, 16, 8, 4, 256>(sA, sW, threadIdx.x, 512,
        [&](int k, int m) { return cnn[(m0 + m) * 512 + k]; },
        [&](int k, int n) { return W[k * 512 + n0 + n]; },
        [&](int mi, int nj, float v) {
            Cout[(m0 + mi) * 512 + n0 + nj] = v + bias[n0 + nj]; });
}

// ================= unified 128x128 cp.async bf16 GEMM pipeline ==============
#define ASTR 40
#define BSTR 136
#define ABUFB (128 * ASTR)
#define BBUFB (32 * BSTR)
#define BIGSMEM ((4 * ABUFB + 4 * BBUFB) * 2)   // bytes

__device__ __forceinline__ void big_pipe(
    const bf16 *Ah, const bf16 *Al,
    const bf16 *Bh, const bf16 *Bl, size_t bpitch,
    float acc[2][8][4])
{
    extern __shared__ bf16 dsm[];
    bf16 *sAh = dsm, *sAl = dsm + 2 * ABUFB;
    bf16 *sBh = dsm + 4 * ABUFB, *sBl = dsm + 4 * ABUFB + 2 * BBUFB;

    const int tid = threadIdx.x, lane = tid & 31, w = tid >> 5;
    const int wm = (w & 3) * 32, wn = (w >> 2) * 64;

    auto issue = [&](int kb, int buf) {
#pragma unroll
        for (int j = 0; j < 2; j++) {
            int c = tid + j * 256;                     // 512 A-chunks of 8 bf16
            int r = c >> 2, k8 = (c & 3) * 8;
            size_t off = (size_t)r * 512 + kb + k8;
            unsigned d = buf * ABUFB + r * ASTR + k8;
            cpa16(s2u(sAh) + d * 2, Ah + off);
            cpa16(s2u(sAl) + d * 2, Al + off);
        }
#pragma unroll
        for (int j = 0; j < 2; j++) {
            int c = tid + j * 256;                     // 512 B-chunks
            int kr = c >> 4, n8 = (c & 15) * 8;
            size_t off = (size_t)(kb + kr) * bpitch + n8;
            unsigned d = buf * BBUFB + kr * BSTR + n8;
            cpa16(s2u(sBh) + d * 2, Bh + off);
            cpa16(s2u(sBl) + d * 2, Bl + off);
        }
    };
    auto comp = [&](int buf) {
        const bf16 *ah_ = sAh + buf * ABUFB, *al_ = sAl + buf * ABUFB;
        const bf16 *bh_ = sBh + buf * BBUFB, *bl_ = sBl + buf * BBUFB;
#pragma unroll
        for (int ks = 0; ks < 2; ks++) {
            unsigned ah[2][4], al[2][4];
#pragma unroll
            for (int mi = 0; mi < 2; mi++) {
                int row = wm + mi * 16 + (lane & 15);
                unsigned off = row * (ASTR * 2) + ks * 32 + (lane >> 4) * 16;
                LDMX4(ah[mi], s2u(ah_) + off);
                LDMX4(al[mi], s2u(al_) + off);
            }
#pragma unroll
            for (int np = 0; np < 4; np++) {
                int kr = ks * 16 + (lane & 15);
                unsigned off = kr * (BSTR * 2) + (wn + np * 16 + (lane >> 4) * 8) * 2;
                unsigned bh[4], bl[4];
                LDMX4T(bh, s2u(bh_) + off);
                LDMX4T(bl, s2u(bl_) + off);
#pragma unroll
                for (int mi = 0; mi < 2; mi++) {
                    float *d0 = acc[mi][np * 2], *d1 = acc[mi][np * 2 + 1];
                    MMA16816(d0, ah[mi], bh[0], bh[1]);
                    MMA16816(d0, al[mi], bh[0], bh[1]);
                    MMA16816(d0, ah[mi], bl[0], bl[1]);
                    MMA16816(d1, ah[mi], bh[2], bh[3]);
                    MMA16816(d1, al[mi], bh[2], bh[3]);
                    MMA16816(d1, ah[mi], bl[2], bl[3]);
                }
            }
        }
    };

    issue(0, 0); CPA_COMMIT();
    for (int it = 0; it < 16; ++it) {
        __syncthreads();                  // readers of target buffer done
        if (it + 1 < 16) {
            issue((it + 1) << 5, (it + 1) & 1);
            CPA_COMMIT();
            CPA_WAIT(1);
        } else {
            CPA_WAIT(0);
        }
        __syncthreads();                  // buffer 'it&1' visible to all
        comp(it & 1);
    }
}

// embed: P_g[t] = E[t] @ Wx_g + C_g
__global__ __launch_bounds__(256, 2) void k_embed_tc()
{
    const int t = blockIdx.y, g = blockIdx.z, n0 = blockIdx.x * 128;
    const int lane = threadIdx.x & 31, w = threadIdx.x >> 5;
    const int wm = (w & 3) * 32, wn = (w >> 2) * 64;

    float acc[2][8][4];
#pragma unroll
    for (int i = 0; i < 2; i++)
#pragma unroll
        for (int j = 0; j < 8; j++)
#pragma unroll
            for (int q = 0; q < 4; q++) acc[i][j][q] = 0.f;

    big_pipe(g_Eh + (size_t)t * BH, g_El + (size_t)t * BH,
             g_Wh[g] + 512 * 512 + n0, g_Wl[g] + 512 * 512 + n0, 512, acc);

    const float *Cg = g_C[g];
    float *Pg = g_P[g] + (size_t)t * BH;
#pragma unroll
    for (int mi = 0; mi < 2; mi++)
#pragma unroll
        for (int nf = 0; nf < 8; nf++) {
            int row = wm + mi * 16 + (lane >> 2);
            int col = n0 + wn + nf * 8 + 2 * (lane & 3);
            int i1 = row * 512 + col, i2 = (row + 8) * 512 + col;
            Pg[i1]     = acc[mi][nf][0] + Cg[i1];
            Pg[i1 + 1] = acc[mi][nf][1] + Cg[i1 + 1];
            Pg[i2]     = acc[mi][nf][2] + Cg[i2];
            Pg[i2 + 1] = acc[mi][nf][3] + Cg[i2 + 1];
        }
}

// logits: out[b,t,:] = h1seq[t] @ ow + ob
__global__ __launch_bounds__(256, 2) void k_logits_tc(
    const float * __restrict__ ob, float * __restrict__ out)
{
    const int t = blockIdx.y, n0 = blockIdx.x * 128;
    const int lane = threadIdx.x & 31, w = threadIdx.x >> 5;
    const int wm = (w & 3) * 32, wn = (w >> 2) * 64;

    float acc[2][8][4];
#pragma unroll
    for (int i = 0; i < 2; i++)
#pragma unroll
        for (int j = 0; j < 8; j++)
#pragma unroll
            for (int q = 0; q < 4; q++) acc[i][j][q] = 0.f;

    big_pipe(g_Sh + (size_t)t * BH, g_Sl + (size_t)t * BH,
             g_OWh + n0, g_OWl + n0, VPAD, acc);

#pragma unroll
    for (int mi = 0; mi < 2; mi++)
#pragma unroll
        for (int nf = 0; nf < 8; nf++) {
            int row = wm + mi * 16 + (lane >> 2);
            int col = n0 + wn + nf * 8 + 2 * (lane & 3);
            if (col < VOCq) {
                float bb = ob[col], bb1 = (col + 1 < VOCq) ? ob[col + 1] : 0.f;
                size_t b1i = ((size_t)row * Tq + t) * VOCq;
                size_t b2i = ((size_t)(row + 8) * Tq + t) * VOCq;
                out[b1i + col] = acc[mi][nf][0] + bb;
                if (col + 1 < VOCq) out[b1i + col + 1] = acc[mi][nf][1] + bb1;
                out[b2i + col] = acc[mi][nf][2] + bb;
                if (col + 1 < VOCq) out[b2i + col + 1] = acc[mi][nf][3] + bb1;
            }
        }
}

__global__ void k_hidden(float *out)
{
    int i = blockIdx.x * blockDim.x + threadIdx.x;
    if (i < BH) { out[i] = g_H0B[1][i]; out[BH + i] = g_H1[i]; }
}

extern "C" void kernel_launch(void *const *d_in, const int *in_sizes, int n_in,
                              void *d_out, int out_size)
{
    const int   *tokens = (const int *)  d_in[0];
    const float *cnn    = (const float *)d_in[1];
    const float *emb    = (const float *)d_in[2];
    const float *wu0 = (const float *)d_in[3],  *bu0 = (const float *)d_in[4];
    const float *wr0 = (const float *)d_in[5],  *br0 = (const float *)d_in[6];
    const float *wc0 = (const float *)d_in[7],  *bc0 = (const float *)d_in[8];
    const float *wu1 = (const float *)d_in[9],  *bu1 = (const float *)d_in[10];
    const float *wr1 = (const float *)d_in[11], *br1 = (const float *)d_in[12];
    const float *wc1 = (const float *)d_in[13], *bc1 = (const float *)d_in[14];
    const float *ow  = (const float *)d_in[15], *ob  = (const float *)d_in[16];
    float *out = (float *)d_out;

    static bool attrDone = false;
    if (!attrDone) {
        cudaFuncSetAttribute(k_embed_tc,
            cudaFuncAttributeMaxDynamicSharedMemorySize, BIGSMEM);
        cudaFuncSetAttribute(k_logits_tc,
            cudaFuncAttributeMaxDynamicSharedMemorySize, BIGSMEM);
        attrDone = true;
    }

    k_init<<<128, 512>>>();
    k_prep<<<dim3(256, 6), 256>>>(wu0, wr0, wc0, wu1, wr1, wc1);
    k_prep_ow<<<2048, 256>>>(ow);
    k_eprep<<<2048, 256>>>(tokens, emb);
    k_cnn <<<dim3(8, 1, 3), 256>>>(cnn, wu0, wr0, wc0, bu0, br0, bc0);
    k_embed_tc<<<dim3(4, Tq, 3), 256, BIGSMEM>>>();

    k_recur<<<NBLK, 256>>>(bu1, br1, bc1);

    k_logits_tc<<<dim3(79, Tq), 256, BIGSMEM>>>(ob, out);

    if (out_size >= (int)((size_t)Tq * 128 * VOCq + 2 * BH)) {
        k_hidden<<<128, 512>>>(out + (size_t)Tq * 128 * VOCq);
    }
}